// round 10
// baseline (speedup 1.0000x reference)
#include <cuda_runtime.h>
#include <cuda_bf16.h>
#include <mma.h>
#include <cstdint>
#include <cstddef>
#include <math.h>

using namespace nvcuda;

constexpr int B_ = 64, N_ = 512, C_ = 16, D_ = 64, T_ = 32;
constexpr int VND = B_ * N_ * D_;
constexpr int CDD = B_ * C_ * D_;
constexpr int MAXDEG = 160;

constexpr int LDA = 136;   // smem A tile [64][LDA] bf16 (bank-spread padding)
constexpr int LDG_ = 272;  // gates [64][LDG_] f32

// ---------------- state (device globals; allocation-free) ----------------
__device__ float g_vh0[2][VND];
__device__ float g_vh1[2][VND];
__device__ float g_vc0[2][VND];
__device__ float g_vc1[2][VND];
__device__ float g_ch[2][CDD];
__device__ float g_cc[2][CDD];
__device__ float g_mv[VND];
__device__ float g_vpart[B_ * 8 * 64];
__device__ float g_mcg[B_ * 256];
__device__ unsigned short g_nbr[(size_t)B_ * N_ * MAXDEG];
__device__ int g_deg[B_ * N_];
// bf16 hi/lo weight images, row-major [K=128][N=256] (read via L2 by wmma)
__device__ __nv_bfloat16 g_W1hi[32768], g_W1lo[32768];
__device__ __nv_bfloat16 g_W0hi[32768], g_W0lo[32768];

__device__ __forceinline__ float sigf(float x)     { return 1.0f / (1.0f + __expf(-x)); }
__device__ __forceinline__ float tanhfast(float x) { return 2.0f / (1.0f + __expf(-2.0f * x)) - 1.0f; }

// ---------------- adjacency build ----------------
__global__ void k_adj(const float* __restrict__ Mvv)
{
    int gw = (blockIdx.x * blockDim.x + threadIdx.x) >> 5;
    int lane = threadIdx.x & 31;
    if (gw >= B_ * N_) return;
    const float* row = Mvv + (size_t)gw * N_;
    unsigned short* outp = g_nbr + (size_t)gw * MAXDEG;
    int cnt = 0;
    for (int base = 0; base < N_; base += 32) {
        float v = row[base + lane];
        unsigned m = __ballot_sync(0xffffffffu, v != 0.0f);
        if (v != 0.0f) {
            int pos = cnt + __popc(m & ((1u << lane) - 1u));
            if (pos < MAXDEG) outp[pos] = (unsigned short)(base + lane);
        }
        cnt += __popc(m);
    }
    if (lane == 0) g_deg[gw] = cnt < MAXDEG ? cnt : MAXDEG;
}

__global__ void k_init(const float* __restrict__ vh0i, const float* __restrict__ vh1i,
                       const float* __restrict__ chi)
{
    int i = blockIdx.x * blockDim.x + threadIdx.x;
    if (i < VND) {
        g_vh0[0][i] = vh0i[i];
        g_vh1[0][i] = vh1i[i];
        g_vc0[0][i] = 0.f;
        g_vc1[0][i] = 0.f;
    }
    if (i < CDD) { g_ch[0][i] = chi[i]; g_cc[0][i] = 0.f; }
}

// ---------------- weight image build (once per replay) -------------------
// W1 = [Wih1;Whh1], W0 = [Wih0[64:];Whh0], row-major [128][256], bf16 hi/lo
__global__ void k_prepw(const float* __restrict__ Wih0, const float* __restrict__ Whh0,
                        const float* __restrict__ Wih1, const float* __restrict__ Whh1)
{
    int idx = blockIdx.x * blockDim.x + threadIdx.x;   // 0..65535
    if (idx >= 65536) return;
    int mat = idx >> 15;
    int rem = idx & 32767;
    int k = rem >> 8;      // 0..127
    int n = rem & 255;     // 0..255
    float v;
    if (mat == 0) v = (k < 64) ? Wih1[k * 256 + n]        : Whh1[(k - 64) * 256 + n];
    else          v = (k < 64) ? Wih0[(64 + k) * 256 + n] : Whh0[(k - 64) * 256 + n];
    __nv_bfloat16 h = __float2bfloat16(v);
    __nv_bfloat16 l = __float2bfloat16(v - __bfloat162float(h));
    if (mat == 0) { g_W1hi[k * 256 + n] = h; g_W1lo[k * 256 + n] = l; }
    else          { g_W0hi[k * 256 + n] = h; g_W0lo[k * 256 + n] = l; }
}

// stage two fp32 sources as bf16 hi/lo A tile [64][LDA]
__device__ __forceinline__ void stage_a(__nv_bfloat16* Ah, __nv_bfloat16* Al, int tid,
                                        const float* src0, const float* src1)
{
    for (int i = tid; i < 4096; i += 256) {
        int r = i >> 6, k = (i & 63) * 2;
        float2 v = (k < 64) ? *(const float2*)(src0 + r * 64 + k)
                            : *(const float2*)(src1 + r * 64 + k - 64);
        __nv_bfloat162 h2 = __float22bfloat162_rn(v);
        float2 bk; bk.x = __bfloat162float(h2.x); bk.y = __bfloat162float(h2.y);
        float2 lo; lo.x = v.x - bk.x; lo.y = v.y - bk.y;
        __nv_bfloat162 l2 = __float22bfloat162_rn(lo);
        *(__nv_bfloat162*)(Ah + r * LDA + k) = h2;
        *(__nv_bfloat162*)(Al + r * LDA + k) = l2;
    }
}

// wmma GEMM: gates[64][LDG_] = A[64][128](smem) @ W[128][256](global), 3-term hi/lo
// warp tile: 16 rows x 64 cols, cg loop over two 64-col groups -> acc[4]
__device__ __forceinline__ void wmma_gemm(const __nv_bfloat16* Ah, const __nv_bfloat16* Al,
                                          const __nv_bfloat16* __restrict__ Wh,
                                          const __nv_bfloat16* __restrict__ Wl,
                                          float* gates, int w)
{
    int rowtile = w >> 1;
    wmma::fragment<wmma::matrix_a, 16, 16, 16, __nv_bfloat16, wmma::row_major> aHi, aLo;
    wmma::fragment<wmma::matrix_b, 16, 16, 16, __nv_bfloat16, wmma::row_major> bHi, bLo;
    #pragma unroll
    for (int cg = 0; cg < 2; cg++) {
        int colbase = (w & 1) * 128 + cg * 64;
        wmma::fragment<wmma::accumulator, 16, 16, 16, float> acc[4];
        #pragma unroll
        for (int ct = 0; ct < 4; ct++) wmma::fill_fragment(acc[ct], 0.0f);
        #pragma unroll
        for (int k = 0; k < 8; k++) {
            wmma::load_matrix_sync(aHi, Ah + rowtile * 16 * LDA + k * 16, LDA);
            wmma::load_matrix_sync(aLo, Al + rowtile * 16 * LDA + k * 16, LDA);
            #pragma unroll
            for (int ct = 0; ct < 4; ct++) {
                const __nv_bfloat16* bp = Wh + (k * 16) * 256 + colbase + ct * 16;
                const __nv_bfloat16* bq = Wl + (k * 16) * 256 + colbase + ct * 16;
                wmma::load_matrix_sync(bHi, bp, 256);
                wmma::load_matrix_sync(bLo, bq, 256);
                wmma::mma_sync(acc[ct], aHi, bHi, acc[ct]);
                wmma::mma_sync(acc[ct], aHi, bLo, acc[ct]);
                wmma::mma_sync(acc[ct], aLo, bHi, acc[ct]);
            }
        }
        #pragma unroll
        for (int ct = 0; ct < 4; ct++)
            wmma::store_matrix_sync(gates + rowtile * 16 * LDG_ + colbase + ct * 16,
                                    acc[ct], LDG_, wmma::mem_row_major);
    }
}

// ---------------- smem layout (floats from dynamic base) -----------------
// A tiles (bf16): bytes 0..34,816  == floats 0..8,704
// gates: floats 8,704..26,112  (disjoint from A; no overlay hazard)
// post-GEMM overlays: W1@0 (6,400, over dead A), R@6,400 (256)
// post-activation:    X1@8,704 (4,352, over dead gates), H@13,056 (6,656), W2@19,712 (6,400)
constexpr int SMEM_AB = 26112 * 4;   // 104,448 B -> 2 blocks/SM
constexpr int F_GATES = 8704;
constexpr int F_W1 = 0, F_R = 6400, F_X1 = 8704, F_H = 13056, F_W2 = 19712;

// ---------------- kernel A: mv gather + LSTM1 (wmma) + vmsg MLP ----------
// grid = 512 (64 batches x 8 tiles of 64 rows), 256 threads, 2 blocks/SM
__global__ __launch_bounds__(256, 2)
void k_stepA(int old, const float* __restrict__ bih1, const float* __restrict__ bhh1,
             const float* __restrict__ vW1, const float* __restrict__ vb1,
             const float* __restrict__ vW2, const float* __restrict__ vb2)
{
    extern __shared__ float smf[];
    __nv_bfloat16* Ah = (__nv_bfloat16*)smf;
    __nv_bfloat16* Al = Ah + 64 * LDA;
    float* gates = smf + F_GATES;
    __shared__ float bsum[256];
    const int tid = threadIdx.x;
    const int lane = tid & 31, w = tid >> 5;
    const int b = blockIdx.x >> 3;
    const int tile = blockIdx.x & 7;
    const int row0 = tile * 64;
    const size_t base = ((size_t)b * N_ + row0) * D_;
    const int nw = 1 - old;

    bsum[tid] = bih1[tid] + bhh1[tid];
    stage_a(Ah, Al, tid, g_vh0[old] + base, g_vh1[old] + base);

    // sparse mv gather (global->global; overlaps staging latency)
    {
        const float* vh1b = g_vh1[old] + (size_t)b * N_ * D_;
        for (int r = w; r < 64; r += 8) {
            int n = row0 + r;
            int deg = g_deg[b * N_ + n];
            const unsigned short* nb = g_nbr + ((size_t)(b * N_ + n)) * MAXDEG;
            float a0 = 0.f, a1 = 0.f, b0 = 0.f, b1 = 0.f, c0 = 0.f, c1 = 0.f, d0 = 0.f, d1 = 0.f;
            int k = 0;
            for (; k + 4 <= deg; k += 4) {
                float2 v0 = *(const float2*)(vh1b + (size_t)nb[k]     * D_ + lane * 2);
                float2 v1 = *(const float2*)(vh1b + (size_t)nb[k + 1] * D_ + lane * 2);
                float2 v2 = *(const float2*)(vh1b + (size_t)nb[k + 2] * D_ + lane * 2);
                float2 v3 = *(const float2*)(vh1b + (size_t)nb[k + 3] * D_ + lane * 2);
                a0 += v0.x; a1 += v0.y; b0 += v1.x; b1 += v1.y;
                c0 += v2.x; c1 += v2.y; d0 += v3.x; d1 += v3.y;
            }
            for (; k < deg; k++) {
                float2 v = *(const float2*)(vh1b + (size_t)nb[k] * D_ + lane * 2);
                a0 += v.x; a1 += v.y;
            }
            *((float2*)(g_mv + ((size_t)b * N_ + n) * D_) + lane) =
                make_float2(a0 + b0 + c0 + d0, a1 + b1 + c1 + d1);
        }
    }
    __syncthreads();

    wmma_gemm(Ah, Al, g_W1hi, g_W1lo, gates, w);
    __syncthreads();

    // activation (reads gates) + stage MLP W1 over dead A-tile region
    {
        const float* vc1o = g_vc1[old] + base;
        float* vh1n = g_vh1[nw] + base;
        float* vc1n = g_vc1[nw] + base;
        for (int i = tid; i < 4096; i += 256) {
            int r = i >> 6, d = i & 63;
            float gi = gates[r * LDG_ + d]       + bsum[d];
            float gf = gates[r * LDG_ + 64 + d]  + bsum[64 + d];
            float gg = gates[r * LDG_ + 128 + d] + bsum[128 + d];
            float go = gates[r * LDG_ + 192 + d] + bsum[192 + d];
            float c2 = sigf(gf) * vc1o[i] + sigf(gi) * tanhfast(gg);
            vc1n[i] = c2;
            vh1n[i] = sigf(go) * tanhfast(c2);
        }
        const float4* p1 = (const float4*)vW1;
        for (int i = tid; i < 1600; i += 256) ((float4*)(smf + F_W1))[i] = p1[i];
    }
    __syncthreads();

    // stage X1 (vh1_old) + W2 over dead gates region
    {
        const float4* px = (const float4*)(g_vh1[old] + base);
        for (int i = tid; i < 1024; i += 256) {
            int r = i >> 4, q = i & 15;
            *(float4*)(smf + F_X1 + r * 68 + q * 4) = px[i];
        }
        const float4* p2 = (const float4*)vW2;
        for (int i = tid; i < 1600; i += 256) ((float4*)(smf + F_W2))[i] = p2[i];
    }
    __syncthreads();

    // vmsg MLP layer 1: 64 rows x 100 hidden
    {
        float* X1 = smf + F_X1;
        float* W1 = smf + F_W1;
        float* H  = smf + F_H;
        for (int idx = tid; idx < 6400; idx += 256) {
            int r = idx / 100, h = idx - r * 100;
            float a0 = 0.f, a1 = 0.f;
            #pragma unroll 8
            for (int k = 0; k < 64; k += 2) {
                a0 = fmaf(X1[r * 68 + k],     W1[k * 100 + h],       a0);
                a1 = fmaf(X1[r * 68 + k + 1], W1[(k + 1) * 100 + h], a1);
            }
            H[r * 104 + h] = fmaxf(a0 + a1 + vb1[h], 0.f);
        }
    }
    __syncthreads();
    // layer 2 + relu into V (=X1 region), then row-sum reduction
    {
        float* W2 = smf + F_W2;
        float* H  = smf + F_H;
        float* V  = smf + F_X1;
        int rr = tid >> 2, dg = tid & 3;
        float a2[16];
        #pragma unroll
        for (int i = 0; i < 16; i++) a2[i] = 0.f;
        for (int k = 0; k < 100; k++) {
            float x = H[rr * 104 + k];
            #pragma unroll
            for (int i = 0; i < 16; i++)
                a2[i] = fmaf(x, W2[k * 64 + dg * 16 + i], a2[i]);
        }
        #pragma unroll
        for (int i = 0; i < 16; i++)
            V[rr * 68 + dg * 16 + i] = fmaxf(a2[i] + vb2[dg * 16 + i], 0.f);
        __syncthreads();
        float* R = smf + F_R;
        int q = tid >> 6, d = tid & 63;
        float s = 0.f;
        #pragma unroll
        for (int r = 0; r < 16; r++) s += V[(q * 16 + r) * 68 + d];
        R[q * 64 + d] = s;
        __syncthreads();
        if (tid < 64)
            g_vpart[(b * 8 + tile) * 64 + tid] =
                R[tid] + R[64 + tid] + R[128 + tid] + R[192 + tid];
    }
}

// ---------------- kernel B: LSTM0 (wmma); grid = 512, 2 blocks/SM --------
__global__ __launch_bounds__(256, 2)
void k_stepB(int old)
{
    extern __shared__ float smf[];
    __nv_bfloat16* Ah = (__nv_bfloat16*)smf;
    __nv_bfloat16* Al = Ah + 64 * LDA;
    float* gates = smf + F_GATES;
    __shared__ float bsum[256];
    const int tid = threadIdx.x;
    const int w = tid >> 5;
    const int b = blockIdx.x >> 3;
    const int tile = blockIdx.x & 7;
    const int row0 = tile * 64;
    const size_t base = ((size_t)b * N_ + row0) * D_;
    const int nw = 1 - old;

    bsum[tid] = g_mcg[b * 256 + tid];
    stage_a(Ah, Al, tid, g_mv + base, g_vh0[old] + base);
    __syncthreads();

    wmma_gemm(Ah, Al, g_W0hi, g_W0lo, gates, w);
    __syncthreads();

    {
        const float* vc0o = g_vc0[old] + base;
        float* vh0n = g_vh0[nw] + base;
        float* vc0n = g_vc0[nw] + base;
        for (int i = tid; i < 4096; i += 256) {
            int r = i >> 6, d = i & 63;
            float gi = gates[r * LDG_ + d]       + bsum[d];
            float gf = gates[r * LDG_ + 64 + d]  + bsum[64 + d];
            float gg = gates[r * LDG_ + 128 + d] + bsum[128 + d];
            float go = gates[r * LDG_ + 192 + d] + bsum[192 + d];
            float c2 = sigf(gf) * vc0o[i] + sigf(gi) * tanhfast(gg);
            vc0n[i] = c2;
            vh0n[i] = sigf(go) * tanhfast(c2);
        }
    }
}

// ---------------- kernel C: color-side; grid = 64, 256 threads -----------
__global__ __launch_bounds__(256, 1)
void k_stepC(int old, const int* __restrict__ n_colors,
             const float* __restrict__ cW1, const float* __restrict__ cb1,
             const float* __restrict__ cW2, const float* __restrict__ cb2,
             const float* __restrict__ Wih0, const float* __restrict__ bih0,
             const float* __restrict__ bhh0,
             const float* __restrict__ Wihc, const float* __restrict__ Whhc,
             const float* __restrict__ bihc, const float* __restrict__ bhhc)
{
    extern __shared__ float sm[];
    float* vsum  = sm;                // 64
    float* chs   = vsum + 64;         // 1024
    float* cW1s  = chs + 1024;        // 6400
    float* cW2s  = cW1s + 6400;       // 6400
    float* hid   = cW2s + 6400;       // 1664
    float* cmsgs = hid + 1664;        // 1024
    float* mcv   = cmsgs + 1024;      // 64
    float* xps   = mcv + 64;          // 256
    float* Whhcs = xps + 256;         // 16384
    float* gcs   = Whhcs + 16384;     // 4160

    const int tid = threadIdx.x;
    const int b = blockIdx.x;
    const int nw = 1 - old;
    const int nc = n_colors[b];

    if (tid < 64) {
        float s = 0.f;
        #pragma unroll
        for (int blk = 0; blk < 8; blk++) s += g_vpart[(b * 8 + blk) * 64 + tid];
        vsum[tid] = s;
    }
    {
        const float4* pc = (const float4*)(g_ch[old] + b * 1024);
        for (int i = tid; i < 256; i += 256) ((float4*)chs)[i] = pc[i];
        const float4* p1 = (const float4*)cW1;
        const float4* p2 = (const float4*)cW2;
        for (int i = tid; i < 1600; i += 256) {
            ((float4*)cW1s)[i] = p1[i];
            ((float4*)cW2s)[i] = p2[i];
        }
        const float4* pw = (const float4*)Whhc;
        for (int i = tid; i < 4096; i += 256) ((float4*)Whhcs)[i] = pw[i];
    }
    __syncthreads();

    for (int idx = tid; idx < 16 * 100; idx += 256) {
        int c = idx / 100, h = idx % 100;
        float a0 = 0.f, a1 = 0.f;
        #pragma unroll 8
        for (int d = 0; d < 64; d += 2) {
            a0 = fmaf(chs[c * 64 + d],     cW1s[d * 100 + h],       a0);
            a1 = fmaf(chs[c * 64 + d + 1], cW1s[(d + 1) * 100 + h], a1);
        }
        hid[c * 104 + h] = fmaxf(a0 + a1 + cb1[h], 0.f);
    }
    __syncthreads();
    for (int idx = tid; idx < 1024; idx += 256) {
        int c = idx >> 6, d = idx & 63;
        float a0 = 0.f, a1 = 0.f;
        #pragma unroll 10
        for (int h = 0; h < 100; h += 2) {
            a0 = fmaf(hid[c * 104 + h],     cW2s[h * 64 + d],       a0);
            a1 = fmaf(hid[c * 104 + h + 1], cW2s[(h + 1) * 64 + d], a1);
        }
        cmsgs[idx] = fmaxf(a0 + a1 + cb2[d], 0.f);
    }
    __syncthreads();
    if (tid < 64) {
        float s = 0.f;
        for (int c = 0; c < nc; c++) s += cmsgs[c * 64 + tid];
        mcv[tid] = s;
    }
    __syncthreads();
    {
        int g = tid;
        float a0 = bih0[g] + bhh0[g], a1 = 0.f;
        float x0 = 0.f, x1 = 0.f;
        #pragma unroll 8
        for (int d = 0; d < 64; d += 2) {
            a0 = fmaf(mcv[d],      Wih0[d * 256 + g],       a0);
            a1 = fmaf(mcv[d + 1],  Wih0[(d + 1) * 256 + g], a1);
            x0 = fmaf(vsum[d],     Wihc[d * 256 + g],       x0);
            x1 = fmaf(vsum[d + 1], Wihc[(d + 1) * 256 + g], x1);
        }
        g_mcg[b * 256 + g] = a0 + a1;
        xps[g] = x0 + x1;
    }
    __syncthreads();
    {
        int c = tid >> 4, seg = (tid & 15) * 16;
        float a[16];
        #pragma unroll
        for (int i = 0; i < 16; i++) a[i] = 0.f;
        for (int k = 0; k < 64; k++) {
            float x = chs[c * 64 + k];
            const float4* wrow = (const float4*)(Whhcs + k * 256 + seg);
            float4 w0 = wrow[0], w1 = wrow[1], w2 = wrow[2], w3 = wrow[3];
            a[0]  = fmaf(x, w0.x, a[0]);  a[1]  = fmaf(x, w0.y, a[1]);
            a[2]  = fmaf(x, w0.z, a[2]);  a[3]  = fmaf(x, w0.w, a[3]);
            a[4]  = fmaf(x, w1.x, a[4]);  a[5]  = fmaf(x, w1.y, a[5]);
            a[6]  = fmaf(x, w1.z, a[6]);  a[7]  = fmaf(x, w1.w, a[7]);
            a[8]  = fmaf(x, w2.x, a[8]);  a[9]  = fmaf(x, w2.y, a[9]);
            a[10] = fmaf(x, w2.z, a[10]); a[11] = fmaf(x, w2.w, a[11]);
            a[12] = fmaf(x, w3.x, a[12]); a[13] = fmaf(x, w3.y, a[13]);
            a[14] = fmaf(x, w3.z, a[14]); a[15] = fmaf(x, w3.w, a[15]);
        }
        float mk = (c < nc) ? 1.f : 0.f;
        #pragma unroll
        for (int i = 0; i < 16; i++) {
            int g = seg + i;
            gcs[c * 260 + g] = a[i] + mk * xps[g] + bihc[g] + bhhc[g];
        }
    }
    __syncthreads();
    {
        const float* cco = g_cc[old] + b * 1024;
        float* chn = g_ch[nw] + b * 1024;
        float* ccn = g_cc[nw] + b * 1024;
        for (int i = tid; i < 1024; i += 256) {
            int c = i >> 6, d = i & 63;
            float gi  = gcs[c * 260 + d];
            float gf  = gcs[c * 260 + 64 + d];
            float gg2 = gcs[c * 260 + 128 + d];
            float go  = gcs[c * 260 + 192 + d];
            float c2 = sigf(gf) * cco[i] + sigf(gi) * tanhfast(gg2);
            ccn[i] = c2;
            chn[i] = sigf(go) * tanhfast(c2);
        }
    }
}

// ---------------- vote head ----------------------------------------------
__global__ void k_vote(const float* __restrict__ W1, const float* __restrict__ b1,
                       const float* __restrict__ W2, const float* __restrict__ b2,
                       float* __restrict__ out)
{
    __shared__ float w1s[64 * 16];
    __shared__ float w2s[16];
    __shared__ float red[256];
    const int tid = threadIdx.x, b = blockIdx.x;
    for (int i = tid; i < 64 * 16; i += 256) w1s[i] = W1[i];
    if (tid < 16) w2s[tid] = W2[tid];
    __syncthreads();

    float acc = 0.f;
    for (int r = tid; r < N_; r += 256) {
        const float* x = g_vh1[0] + ((size_t)b * N_ + r) * D_;
        float h[16];
        #pragma unroll
        for (int j = 0; j < 16; j++) h[j] = b1[j];
        for (int k = 0; k < 64; k++) {
            float xv = x[k];
            #pragma unroll
            for (int j = 0; j < 16; j++) h[j] = fmaf(xv, w1s[k * 16 + j], h[j]);
        }
        float v = b2[0];
        #pragma unroll
        for (int j = 0; j < 16; j++) v += sigf(h[j]) * w2s[j];
        acc += sigf(v);
    }
    red[tid] = acc;
    __syncthreads();
    for (int s = 128; s > 0; s >>= 1) {
        if (tid < s) red[tid] += red[tid + s];
        __syncthreads();
    }
    if (tid == 0) out[b] = sigf(red[0] / (float)N_);
}

// ---------------- launch -------------------------------------------------
extern "C" void kernel_launch(void* const* d_in, const int* in_sizes, int n_in,
                              void* d_out, int out_size)
{
    const float* Mvv      = (const float*)d_in[0];
    const int*   n_colors = (const int*)d_in[1];
    const float* vh0i     = (const float*)d_in[2];
    const float* vh1i     = (const float*)d_in[3];
    const float* chi      = (const float*)d_in[4];
    const float* Wih0 = (const float*)d_in[5];
    const float* Whh0 = (const float*)d_in[6];
    const float* bih0 = (const float*)d_in[7];
    const float* bhh0 = (const float*)d_in[8];
    const float* Wih1 = (const float*)d_in[9];
    const float* Whh1 = (const float*)d_in[10];
    const float* bih1 = (const float*)d_in[11];
    const float* bhh1 = (const float*)d_in[12];
    const float* Wihc = (const float*)d_in[13];
    const float* Whhc = (const float*)d_in[14];
    const float* bihc = (const float*)d_in[15];
    const float* bhhc = (const float*)d_in[16];
    const float* cW1 = (const float*)d_in[17];
    const float* cb1 = (const float*)d_in[18];
    const float* cW2 = (const float*)d_in[19];
    const float* cb2 = (const float*)d_in[20];
    const float* vW1 = (const float*)d_in[21];
    const float* vb1 = (const float*)d_in[22];
    const float* vW2 = (const float*)d_in[23];
    const float* vb2 = (const float*)d_in[24];
    const float* voteW1 = (const float*)d_in[25];
    const float* voteb1 = (const float*)d_in[26];
    const float* voteW2 = (const float*)d_in[27];
    const float* voteb2 = (const float*)d_in[28];
    float* out = (float*)d_out;

    const int SMEM_C = 37440 * 4;
    cudaFuncSetAttribute(k_stepA, cudaFuncAttributeMaxDynamicSharedMemorySize, SMEM_AB);
    cudaFuncSetAttribute(k_stepB, cudaFuncAttributeMaxDynamicSharedMemorySize, SMEM_AB);
    cudaFuncSetAttribute(k_stepC, cudaFuncAttributeMaxDynamicSharedMemorySize, SMEM_C);

    k_adj<<<(B_ * N_ * 32 + 255) / 256, 256>>>(Mvv);
    k_init<<<(VND + 255) / 256, 256>>>(vh0i, vh1i, chi);
    k_prepw<<<256, 256>>>(Wih0, Whh0, Wih1, Whh1);

    for (int t = 0; t < T_; t++) {
        int old = t & 1;
        k_stepA<<<512, 256, SMEM_AB>>>(old, bih1, bhh1, vW1, vb1, vW2, vb2);
        k_stepC<<<64, 256, SMEM_C>>>(old, n_colors, cW1, cb1, cW2, cb2,
                                     Wih0, bih0, bhh0, Wihc, Whhc, bihc, bhhc);
        k_stepB<<<512, 256, SMEM_AB>>>(old);
    }
    k_vote<<<B_, 256>>>(voteW1, voteb1, voteW2, voteb2, out);
}

// round 12
// speedup vs baseline: 1.0158x; 1.0158x over previous
#include <cuda_runtime.h>
#include <cuda_bf16.h>
#include <mma.h>
#include <cstdint>
#include <cstddef>
#include <math.h>

using namespace nvcuda;

constexpr int B_ = 64, N_ = 512, C_ = 16, D_ = 64, T_ = 32;
constexpr int VND = B_ * N_ * D_;
constexpr int CDD = B_ * C_ * D_;
constexpr int MAXDEG = 160;

constexpr int LDA = 136;   // smem A tile [64][LDA] bf16 (bank-spread padding)
constexpr int LDG_ = 272;  // gates [64][LDG_] f32

// ---------------- state (device globals; allocation-free) ----------------
__device__ float g_vh0[2][VND];
__device__ float g_vh1[2][VND];
__device__ float g_vc0[2][VND];
__device__ float g_vc1[2][VND];
__device__ float g_ch[2][CDD];
__device__ float g_cc[2][CDD];
__device__ float g_mv[VND];
__device__ float g_vpart[B_ * 8 * 64];
__device__ float g_mcg[B_ * 256];
__device__ unsigned short g_nbr[(size_t)B_ * N_ * MAXDEG];
__device__ int g_deg[B_ * N_];
// bf16 hi/lo weight images, row-major [K=128][N=256] (read via L2 by wmma)
__device__ __nv_bfloat16 g_W1hi[32768], g_W1lo[32768];
__device__ __nv_bfloat16 g_W0hi[32768], g_W0lo[32768];

__device__ __forceinline__ float sigf(float x)     { return 1.0f / (1.0f + __expf(-x)); }
__device__ __forceinline__ float tanhfast(float x) { return 2.0f / (1.0f + __expf(-2.0f * x)) - 1.0f; }

// ---------------- adjacency build ----------------
__global__ void k_adj(const float* __restrict__ Mvv)
{
    int gw = (blockIdx.x * blockDim.x + threadIdx.x) >> 5;
    int lane = threadIdx.x & 31;
    if (gw >= B_ * N_) return;
    const float* row = Mvv + (size_t)gw * N_;
    unsigned short* outp = g_nbr + (size_t)gw * MAXDEG;
    int cnt = 0;
    for (int base = 0; base < N_; base += 32) {
        float v = row[base + lane];
        unsigned m = __ballot_sync(0xffffffffu, v != 0.0f);
        if (v != 0.0f) {
            int pos = cnt + __popc(m & ((1u << lane) - 1u));
            if (pos < MAXDEG) outp[pos] = (unsigned short)(base + lane);
        }
        cnt += __popc(m);
    }
    if (lane == 0) g_deg[gw] = cnt < MAXDEG ? cnt : MAXDEG;
}

__global__ void k_init(const float* __restrict__ vh0i, const float* __restrict__ vh1i,
                       const float* __restrict__ chi)
{
    int i = blockIdx.x * blockDim.x + threadIdx.x;
    if (i < VND) {
        g_vh0[0][i] = vh0i[i];
        g_vh1[0][i] = vh1i[i];
        g_vc0[0][i] = 0.f;
        g_vc1[0][i] = 0.f;
    }
    if (i < CDD) { g_ch[0][i] = chi[i]; g_cc[0][i] = 0.f; }
}

// ---------------- weight image build (once per replay) -------------------
__global__ void k_prepw(const float* __restrict__ Wih0, const float* __restrict__ Whh0,
                        const float* __restrict__ Wih1, const float* __restrict__ Whh1)
{
    int idx = blockIdx.x * blockDim.x + threadIdx.x;   // 0..65535
    if (idx >= 65536) return;
    int mat = idx >> 15;
    int rem = idx & 32767;
    int k = rem >> 8;
    int n = rem & 255;
    float v;
    if (mat == 0) v = (k < 64) ? Wih1[k * 256 + n]        : Whh1[(k - 64) * 256 + n];
    else          v = (k < 64) ? Wih0[(64 + k) * 256 + n] : Whh0[(k - 64) * 256 + n];
    __nv_bfloat16 h = __float2bfloat16(v);
    __nv_bfloat16 l = __float2bfloat16(v - __bfloat162float(h));
    if (mat == 0) { g_W1hi[k * 256 + n] = h; g_W1lo[k * 256 + n] = l; }
    else          { g_W0hi[k * 256 + n] = h; g_W0lo[k * 256 + n] = l; }
}

// stage two fp32 sources as bf16 hi/lo A tile [64][LDA]
__device__ __forceinline__ void stage_a(__nv_bfloat16* Ah, __nv_bfloat16* Al, int tid,
                                        const float* src0, const float* src1)
{
    for (int i = tid; i < 4096; i += 256) {
        int r = i >> 6, k = (i & 63) * 2;
        float2 v = (k < 64) ? *(const float2*)(src0 + r * 64 + k)
                            : *(const float2*)(src1 + r * 64 + k - 64);
        __nv_bfloat162 h2 = __float22bfloat162_rn(v);
        float2 bk; bk.x = __bfloat162float(h2.x); bk.y = __bfloat162float(h2.y);
        float2 lo; lo.x = v.x - bk.x; lo.y = v.y - bk.y;
        __nv_bfloat162 l2 = __float22bfloat162_rn(lo);
        *(__nv_bfloat162*)(Ah + r * LDA + k) = h2;
        *(__nv_bfloat162*)(Al + r * LDA + k) = l2;
    }
}

// wmma GEMM: gates[64][LDG_] = A[64][128](smem) @ W[128][256](global), 3-term hi/lo
__device__ __forceinline__ void wmma_gemm(const __nv_bfloat16* Ah, const __nv_bfloat16* Al,
                                          const __nv_bfloat16* __restrict__ Wh,
                                          const __nv_bfloat16* __restrict__ Wl,
                                          float* gates, int w)
{
    int rowtile = w >> 1;
    wmma::fragment<wmma::matrix_a, 16, 16, 16, __nv_bfloat16, wmma::row_major> aHi, aLo;
    wmma::fragment<wmma::matrix_b, 16, 16, 16, __nv_bfloat16, wmma::row_major> bHi, bLo;
    #pragma unroll
    for (int cg = 0; cg < 2; cg++) {
        int colbase = (w & 1) * 128 + cg * 64;
        wmma::fragment<wmma::accumulator, 16, 16, 16, float> acc[4];
        #pragma unroll
        for (int ct = 0; ct < 4; ct++) wmma::fill_fragment(acc[ct], 0.0f);
        #pragma unroll
        for (int k = 0; k < 8; k++) {
            wmma::load_matrix_sync(aHi, Ah + rowtile * 16 * LDA + k * 16, LDA);
            wmma::load_matrix_sync(aLo, Al + rowtile * 16 * LDA + k * 16, LDA);
            #pragma unroll
            for (int ct = 0; ct < 4; ct++) {
                const __nv_bfloat16* bp = Wh + (k * 16) * 256 + colbase + ct * 16;
                const __nv_bfloat16* bq = Wl + (k * 16) * 256 + colbase + ct * 16;
                wmma::load_matrix_sync(bHi, bp, 256);
                wmma::load_matrix_sync(bLo, bq, 256);
                wmma::mma_sync(acc[ct], aHi, bHi, acc[ct]);
                wmma::mma_sync(acc[ct], aHi, bLo, acc[ct]);
                wmma::mma_sync(acc[ct], aLo, bHi, acc[ct]);
            }
        }
        #pragma unroll
        for (int ct = 0; ct < 4; ct++)
            wmma::store_matrix_sync(gates + rowtile * 16 * LDG_ + colbase + ct * 16,
                                    acc[ct], LDG_, wmma::mem_row_major);
    }
}

// ---------------- kernel GM: mv gather + vmsg MLP (reads vh1_old only) ---
// grid = 512 (64 batches x 8 tiles of 64 rows), 256 threads, 2 blocks/SM
constexpr int SMEM_GM = 24064 * 4;
constexpr int GM_X1 = 0, GM_W1 = 4352, GM_W2 = 10752, GM_H = 17152, GM_R = 23808;

__global__ __launch_bounds__(256, 2)
void k_gm(int old, const float* __restrict__ vW1, const float* __restrict__ vb1,
          const float* __restrict__ vW2, const float* __restrict__ vb2)
{
    extern __shared__ float smf[];
    const int tid = threadIdx.x;
    const int lane = tid & 31, w = tid >> 5;
    const int b = blockIdx.x >> 3;
    const int tile = blockIdx.x & 7;
    const int row0 = tile * 64;
    const size_t base = ((size_t)b * N_ + row0) * D_;

    // stage X1 (vh1_old rows) + W1 + W2
    {
        const float4* px = (const float4*)(g_vh1[old] + base);
        for (int i = tid; i < 1024; i += 256) {
            int r = i >> 4, q = i & 15;
            *(float4*)(smf + GM_X1 + r * 68 + q * 4) = px[i];
        }
        const float4* p1 = (const float4*)vW1;
        const float4* p2 = (const float4*)vW2;
        for (int i = tid; i < 1600; i += 256) {
            ((float4*)(smf + GM_W1))[i] = p1[i];
            ((float4*)(smf + GM_W2))[i] = p2[i];
        }
    }

    // sparse mv gather (overlaps staging latency; independent of smem)
    {
        const float* vh1b = g_vh1[old] + (size_t)b * N_ * D_;
        for (int r = w; r < 64; r += 8) {
            int n = row0 + r;
            int deg = g_deg[b * N_ + n];
            const unsigned short* nb = g_nbr + ((size_t)(b * N_ + n)) * MAXDEG;
            float a0 = 0.f, a1 = 0.f, b0 = 0.f, b1 = 0.f, c0 = 0.f, c1 = 0.f, d0 = 0.f, d1 = 0.f;
            int k = 0;
            for (; k + 4 <= deg; k += 4) {
                float2 v0 = *(const float2*)(vh1b + (size_t)nb[k]     * D_ + lane * 2);
                float2 v1 = *(const float2*)(vh1b + (size_t)nb[k + 1] * D_ + lane * 2);
                float2 v2 = *(const float2*)(vh1b + (size_t)nb[k + 2] * D_ + lane * 2);
                float2 v3 = *(const float2*)(vh1b + (size_t)nb[k + 3] * D_ + lane * 2);
                a0 += v0.x; a1 += v0.y; b0 += v1.x; b1 += v1.y;
                c0 += v2.x; c1 += v2.y; d0 += v3.x; d1 += v3.y;
            }
            for (; k < deg; k++) {
                float2 v = *(const float2*)(vh1b + (size_t)nb[k] * D_ + lane * 2);
                a0 += v.x; a1 += v.y;
            }
            *((float2*)(g_mv + ((size_t)b * N_ + n) * D_) + lane) =
                make_float2(a0 + b0 + c0 + d0, a1 + b1 + c1 + d1);
        }
    }
    __syncthreads();

    // vmsg MLP layer 1: 64 rows x 100 hidden
    {
        float* X1 = smf + GM_X1;
        float* W1 = smf + GM_W1;
        float* H  = smf + GM_H;
        for (int idx = tid; idx < 6400; idx += 256) {
            int r = idx / 100, h = idx - r * 100;
            float a0 = 0.f, a1 = 0.f;
            #pragma unroll 8
            for (int k = 0; k < 64; k += 2) {
                a0 = fmaf(X1[r * 68 + k],     W1[k * 100 + h],       a0);
                a1 = fmaf(X1[r * 68 + k + 1], W1[(k + 1) * 100 + h], a1);
            }
            H[r * 104 + h] = fmaxf(a0 + a1 + vb1[h], 0.f);
        }
    }
    __syncthreads();
    // layer 2 + relu into V (=X1 region), then row-sum reduction
    {
        float* W2 = smf + GM_W2;
        float* H  = smf + GM_H;
        float* V  = smf + GM_X1;
        int rr = tid >> 2, dg = tid & 3;
        float a2[16];
        #pragma unroll
        for (int i = 0; i < 16; i++) a2[i] = 0.f;
        for (int k = 0; k < 100; k++) {
            float x = H[rr * 104 + k];
            #pragma unroll
            for (int i = 0; i < 16; i++)
                a2[i] = fmaf(x, W2[k * 64 + dg * 16 + i], a2[i]);
        }
        __syncthreads();
        #pragma unroll
        for (int i = 0; i < 16; i++)
            V[rr * 68 + dg * 16 + i] = fmaxf(a2[i] + vb2[dg * 16 + i], 0.f);
        __syncthreads();
        float* R = smf + GM_R;
        int q = tid >> 6, d = tid & 63;
        float s = 0.f;
        #pragma unroll
        for (int r = 0; r < 16; r++) s += V[(q * 16 + r) * 68 + d];
        R[q * 64 + d] = s;
        __syncthreads();
        if (tid < 64)
            g_vpart[(b * 8 + tile) * 64 + tid] =
                R[tid] + R[64 + tid] + R[128 + tid] + R[192 + tid];
    }
}

// ---------------- smem layout for A2/B -----------------------------------
constexpr int SMEM_AB = 26112 * 4;   // A tiles (8704 f) + gates (17408 f)
constexpr int F_GATES = 8704;

// ---------------- kernel A2: LSTM1 (stage + wmma + activation) -----------
__global__ __launch_bounds__(256, 2)
void k_stepA2(int old, const float* __restrict__ bih1, const float* __restrict__ bhh1)
{
    extern __shared__ float smf[];
    __nv_bfloat16* Ah = (__nv_bfloat16*)smf;
    __nv_bfloat16* Al = Ah + 64 * LDA;
    float* gates = smf + F_GATES;
    __shared__ float bsum[256];
    const int tid = threadIdx.x;
    const int w = tid >> 5;
    const int b = blockIdx.x >> 3;
    const int tile = blockIdx.x & 7;
    const int row0 = tile * 64;
    const size_t base = ((size_t)b * N_ + row0) * D_;
    const int nw = 1 - old;

    bsum[tid] = bih1[tid] + bhh1[tid];
    stage_a(Ah, Al, tid, g_vh0[old] + base, g_vh1[old] + base);
    __syncthreads();

    wmma_gemm(Ah, Al, g_W1hi, g_W1lo, gates, w);
    __syncthreads();

    {
        const float* vc1o = g_vc1[old] + base;
        float* vh1n = g_vh1[nw] + base;
        float* vc1n = g_vc1[nw] + base;
        for (int i = tid; i < 4096; i += 256) {
            int r = i >> 6, d = i & 63;
            float gi = gates[r * LDG_ + d]       + bsum[d];
            float gf = gates[r * LDG_ + 64 + d]  + bsum[64 + d];
            float gg = gates[r * LDG_ + 128 + d] + bsum[128 + d];
            float go = gates[r * LDG_ + 192 + d] + bsum[192 + d];
            float c2 = sigf(gf) * vc1o[i] + sigf(gi) * tanhfast(gg);
            vc1n[i] = c2;
            vh1n[i] = sigf(go) * tanhfast(c2);
        }
    }
}

// ---------------- kernel B: LSTM0 (stage + wmma + activation) ------------
__global__ __launch_bounds__(256, 2)
void k_stepB(int old)
{
    extern __shared__ float smf[];
    __nv_bfloat16* Ah = (__nv_bfloat16*)smf;
    __nv_bfloat16* Al = Ah + 64 * LDA;
    float* gates = smf + F_GATES;
    __shared__ float bsum[256];
    const int tid = threadIdx.x;
    const int w = tid >> 5;
    const int b = blockIdx.x >> 3;
    const int tile = blockIdx.x & 7;
    const int row0 = tile * 64;
    const size_t base = ((size_t)b * N_ + row0) * D_;
    const int nw = 1 - old;

    bsum[tid] = g_mcg[b * 256 + tid];
    stage_a(Ah, Al, tid, g_mv + base, g_vh0[old] + base);
    __syncthreads();

    wmma_gemm(Ah, Al, g_W0hi, g_W0lo, gates, w);
    __syncthreads();

    {
        const float* vc0o = g_vc0[old] + base;
        float* vh0n = g_vh0[nw] + base;
        float* vc0n = g_vc0[nw] + base;
        for (int i = tid; i < 4096; i += 256) {
            int r = i >> 6, d = i & 63;
            float gi = gates[r * LDG_ + d]       + bsum[d];
            float gf = gates[r * LDG_ + 64 + d]  + bsum[64 + d];
            float gg = gates[r * LDG_ + 128 + d] + bsum[128 + d];
            float go = gates[r * LDG_ + 192 + d] + bsum[192 + d];
            float c2 = sigf(gf) * vc0o[i] + sigf(gi) * tanhfast(gg);
            vc0n[i] = c2;
            vh0n[i] = sigf(go) * tanhfast(c2);
        }
    }
}

// ---------------- kernel C: color-side; grid = 64, 256 threads -----------
// Whhc read straight from global (single-use; staging it was pure overhead)
__global__ __launch_bounds__(256, 1)
void k_stepC(int old, const int* __restrict__ n_colors,
             const float* __restrict__ cW1, const float* __restrict__ cb1,
             const float* __restrict__ cW2, const float* __restrict__ cb2,
             const float* __restrict__ Wih0, const float* __restrict__ bih0,
             const float* __restrict__ bhh0,
             const float* __restrict__ Wihc, const float* __restrict__ Whhc,
             const float* __restrict__ bihc, const float* __restrict__ bhhc)
{
    extern __shared__ float sm[];
    float* vsum  = sm;                // 64
    float* chs   = vsum + 64;         // 1024
    float* cW1s  = chs + 1024;        // 6400
    float* cW2s  = cW1s + 6400;       // 6400
    float* hid   = cW2s + 6400;       // 1664
    float* cmsgs = hid + 1664;        // 1024
    float* mcv   = cmsgs + 1024;      // 64
    float* xps   = mcv + 64;          // 256
    float* gcs   = xps + 256;         // 4160  -> total 21,056 f

    const int tid = threadIdx.x;
    const int b = blockIdx.x;
    const int nw = 1 - old;
    const int nc = n_colors[b];

    if (tid < 64) {
        float s = 0.f;
        #pragma unroll
        for (int blk = 0; blk < 8; blk++) s += g_vpart[(b * 8 + blk) * 64 + tid];
        vsum[tid] = s;
    }
    {
        const float4* pc = (const float4*)(g_ch[old] + b * 1024);
        for (int i = tid; i < 256; i += 256) ((float4*)chs)[i] = pc[i];
        const float4* p1 = (const float4*)cW1;
        const float4* p2 = (const float4*)cW2;
        for (int i = tid; i < 1600; i += 256) {
            ((float4*)cW1s)[i] = p1[i];
            ((float4*)cW2s)[i] = p2[i];
        }
    }
    __syncthreads();

    for (int idx = tid; idx < 16 * 100; idx += 256) {
        int c = idx / 100, h = idx % 100;
        float a0 = 0.f, a1 = 0.f;
        #pragma unroll 8
        for (int d = 0; d < 64; d += 2) {
            a0 = fmaf(chs[c * 64 + d],     cW1s[d * 100 + h],       a0);
            a1 = fmaf(chs[c * 64 + d + 1], cW1s[(d + 1) * 100 + h], a1);
        }
        hid[c * 104 + h] = fmaxf(a0 + a1 + cb1[h], 0.f);
    }
    __syncthreads();
    for (int idx = tid; idx < 1024; idx += 256) {
        int c = idx >> 6, d = idx & 63;
        float a0 = 0.f, a1 = 0.f;
        #pragma unroll 10
        for (int h = 0; h < 100; h += 2) {
            a0 = fmaf(hid[c * 104 + h],     cW2s[h * 64 + d],       a0);
            a1 = fmaf(hid[c * 104 + h + 1], cW2s[(h + 1) * 64 + d], a1);
        }
        cmsgs[idx] = fmaxf(a0 + a1 + cb2[d], 0.f);
    }
    __syncthreads();
    if (tid < 64) {
        float s = 0.f;
        for (int c = 0; c < nc; c++) s += cmsgs[c * 64 + tid];
        mcv[tid] = s;
    }
    __syncthreads();
    {
        int g = tid;
        float a0 = bih0[g] + bhh0[g], a1 = 0.f;
        float x0 = 0.f, x1 = 0.f;
        #pragma unroll 8
        for (int d = 0; d < 64; d += 2) {
            a0 = fmaf(mcv[d],      Wih0[d * 256 + g],       a0);
            a1 = fmaf(mcv[d + 1],  Wih0[(d + 1) * 256 + g], a1);
            x0 = fmaf(vsum[d],     Wihc[d * 256 + g],       x0);
            x1 = fmaf(vsum[d + 1], Wihc[(d + 1) * 256 + g], x1);
        }
        g_mcg[b * 256 + g] = a0 + a1;
        xps[g] = x0 + x1;
    }
    __syncthreads();
    {
        int c = tid >> 4, seg = (tid & 15) * 16;
        float a[16];
        #pragma unroll
        for (int i = 0; i < 16; i++) a[i] = 0.f;
        for (int k = 0; k < 64; k++) {
            float x = chs[c * 64 + k];
            const float4* wrow = (const float4*)(Whhc + k * 256 + seg);
            float4 w0 = wrow[0], w1 = wrow[1], w2 = wrow[2], w3 = wrow[3];
            a[0]  = fmaf(x, w0.x, a[0]);  a[1]  = fmaf(x, w0.y, a[1]);
            a[2]  = fmaf(x, w0.z, a[2]);  a[3]  = fmaf(x, w0.w, a[3]);
            a[4]  = fmaf(x, w1.x, a[4]);  a[5]  = fmaf(x, w1.y, a[5]);
            a[6]  = fmaf(x, w1.z, a[6]);  a[7]  = fmaf(x, w1.w, a[7]);
            a[8]  = fmaf(x, w2.x, a[8]);  a[9]  = fmaf(x, w2.y, a[9]);
            a[10] = fmaf(x, w2.z, a[10]); a[11] = fmaf(x, w2.w, a[11]);
            a[12] = fmaf(x, w3.x, a[12]); a[13] = fmaf(x, w3.y, a[13]);
            a[14] = fmaf(x, w3.z, a[14]); a[15] = fmaf(x, w3.w, a[15]);
        }
        float mk = (c < nc) ? 1.f : 0.f;
        #pragma unroll
        for (int i = 0; i < 16; i++) {
            int g = seg + i;
            gcs[c * 260 + g] = a[i] + mk * xps[g] + bihc[g] + bhhc[g];
        }
    }
    __syncthreads();
    {
        const float* cco = g_cc[old] + b * 1024;
        float* chn = g_ch[nw] + b * 1024;
        float* ccn = g_cc[nw] + b * 1024;
        for (int i = tid; i < 1024; i += 256) {
            int c = i >> 6, d = i & 63;
            float gi  = gcs[c * 260 + d];
            float gf  = gcs[c * 260 + 64 + d];
            float gg2 = gcs[c * 260 + 128 + d];
            float go  = gcs[c * 260 + 192 + d];
            float c2 = sigf(gf) * cco[i] + sigf(gi) * tanhfast(gg2);
            ccn[i] = c2;
            chn[i] = sigf(go) * tanhfast(c2);
        }
    }
}

// ---------------- vote head ----------------------------------------------
__global__ void k_vote(const float* __restrict__ W1, const float* __restrict__ b1,
                       const float* __restrict__ W2, const float* __restrict__ b2,
                       float* __restrict__ out)
{
    __shared__ float w1s[64 * 16];
    __shared__ float w2s[16];
    __shared__ float red[256];
    const int tid = threadIdx.x, b = blockIdx.x;
    for (int i = tid; i < 64 * 16; i += 256) w1s[i] = W1[i];
    if (tid < 16) w2s[tid] = W2[tid];
    __syncthreads();

    float acc = 0.f;
    for (int r = tid; r < N_; r += 256) {
        const float* x = g_vh1[0] + ((size_t)b * N_ + r) * D_;
        float h[16];
        #pragma unroll
        for (int j = 0; j < 16; j++) h[j] = b1[j];
        for (int k = 0; k < 64; k++) {
            float xv = x[k];
            #pragma unroll
            for (int j = 0; j < 16; j++) h[j] = fmaf(xv, w1s[k * 16 + j], h[j]);
        }
        float v = b2[0];
        #pragma unroll
        for (int j = 0; j < 16; j++) v += sigf(h[j]) * w2s[j];
        acc += sigf(v);
    }
    red[tid] = acc;
    __syncthreads();
    for (int s = 128; s > 0; s >>= 1) {
        if (tid < s) red[tid] += red[tid + s];
        __syncthreads();
    }
    if (tid == 0) out[b] = sigf(red[0] / (float)N_);
}

// ---------------- launch -------------------------------------------------
extern "C" void kernel_launch(void* const* d_in, const int* in_sizes, int n_in,
                              void* d_out, int out_size)
{
    const float* Mvv      = (const float*)d_in[0];
    const int*   n_colors = (const int*)d_in[1];
    const float* vh0i     = (const float*)d_in[2];
    const float* vh1i     = (const float*)d_in[3];
    const float* chi      = (const float*)d_in[4];
    const float* Wih0 = (const float*)d_in[5];
    const float* Whh0 = (const float*)d_in[6];
    const float* bih0 = (const float*)d_in[7];
    const float* bhh0 = (const float*)d_in[8];
    const float* Wih1 = (const float*)d_in[9];
    const float* Whh1 = (const float*)d_in[10];
    const float* bih1 = (const float*)d_in[11];
    const float* bhh1 = (const float*)d_in[12];
    const float* Wihc = (const float*)d_in[13];
    const float* Whhc = (const float*)d_in[14];
    const float* bihc = (const float*)d_in[15];
    const float* bhhc = (const float*)d_in[16];
    const float* cW1 = (const float*)d_in[17];
    const float* cb1 = (const float*)d_in[18];
    const float* cW2 = (const float*)d_in[19];
    const float* cb2 = (const float*)d_in[20];
    const float* vW1 = (const float*)d_in[21];
    const float* vb1 = (const float*)d_in[22];
    const float* vW2 = (const float*)d_in[23];
    const float* vb2 = (const float*)d_in[24];
    const float* voteW1 = (const float*)d_in[25];
    const float* voteb1 = (const float*)d_in[26];
    const float* voteW2 = (const float*)d_in[27];
    const float* voteb2 = (const float*)d_in[28];
    float* out = (float*)d_out;

    const int SMEM_C = 21056 * 4;
    cudaFuncSetAttribute(k_gm,     cudaFuncAttributeMaxDynamicSharedMemorySize, SMEM_GM);
    cudaFuncSetAttribute(k_stepA2, cudaFuncAttributeMaxDynamicSharedMemorySize, SMEM_AB);
    cudaFuncSetAttribute(k_stepB,  cudaFuncAttributeMaxDynamicSharedMemorySize, SMEM_AB);
    cudaFuncSetAttribute(k_stepC,  cudaFuncAttributeMaxDynamicSharedMemorySize, SMEM_C);

    k_adj<<<(B_ * N_ * 32 + 255) / 256, 256>>>(Mvv);
    k_init<<<(VND + 255) / 256, 256>>>(vh0i, vh1i, chi);
    k_prepw<<<256, 256>>>(Wih0, Whh0, Wih1, Whh1);

    for (int t = 0; t < T_; t++) {
        int old = t & 1;
        k_gm<<<512, 256, SMEM_GM>>>(old, vW1, vb1, vW2, vb2);
        k_stepC<<<64, 256, SMEM_C>>>(old, n_colors, cW1, cb1, cW2, cb2,
                                     Wih0, bih0, bhh0, Wihc, Whhc, bihc, bhhc);
        k_stepA2<<<512, 256, SMEM_AB>>>(old, bih1, bhh1);
        k_stepB<<<512, 256, SMEM_AB>>>(old);
    }
    k_vote<<<B_, 256>>>(voteW1, voteb1, voteW2, voteb2, out);
}

// round 14
// speedup vs baseline: 1.1038x; 1.0866x over previous
#include <cuda_runtime.h>
#include <cuda_bf16.h>
#include <mma.h>
#include <cstdint>
#include <cstddef>
#include <math.h>

using namespace nvcuda;

constexpr int B_ = 64, N_ = 512, C_ = 16, D_ = 64, T_ = 32;
constexpr int VND = B_ * N_ * D_;
constexpr int CDD = B_ * C_ * D_;
constexpr int MAXDEG = 160;

constexpr int LDA = 136;   // smem A tile [64][LDA] bf16 (bank-spread padding)
constexpr int LDG_ = 272;  // gates [64][LDG_] f32

// ---------------- state (device globals; allocation-free) ----------------
__device__ float g_vh0[2][VND];
__device__ float g_vh1[2][VND];
__device__ float g_vc0[2][VND];
__device__ float g_vc1[2][VND];
__device__ float g_ch[2][CDD];
__device__ float g_cc[2][CDD];
__device__ float g_mv[VND];
__device__ float g_vpart[B_ * 8 * 64];
__device__ float g_mcg[B_ * 256];
__device__ unsigned short g_nbr[(size_t)B_ * N_ * MAXDEG];
__device__ int g_deg[B_ * N_];
// bf16 hi/lo weight images, row-major [K=128][N=256] (read via L2 by wmma)
__device__ __nv_bfloat16 g_W1hi[32768], g_W1lo[32768];
__device__ __nv_bfloat16 g_W0hi[32768], g_W0lo[32768];

__device__ __forceinline__ float sigf(float x)     { return 1.0f / (1.0f + __expf(-x)); }
__device__ __forceinline__ float tanhfast(float x) { return 2.0f / (1.0f + __expf(-2.0f * x)) - 1.0f; }

// ---------------- adjacency build ----------------
__global__ void k_adj(const float* __restrict__ Mvv)
{
    int gw = (blockIdx.x * blockDim.x + threadIdx.x) >> 5;
    int lane = threadIdx.x & 31;
    if (gw >= B_ * N_) return;
    const float* row = Mvv + (size_t)gw * N_;
    unsigned short* outp = g_nbr + (size_t)gw * MAXDEG;
    int cnt = 0;
    for (int base = 0; base < N_; base += 32) {
        float v = row[base + lane];
        unsigned m = __ballot_sync(0xffffffffu, v != 0.0f);
        if (v != 0.0f) {
            int pos = cnt + __popc(m & ((1u << lane) - 1u));
            if (pos < MAXDEG) outp[pos] = (unsigned short)(base + lane);
        }
        cnt += __popc(m);
    }
    if (lane == 0) g_deg[gw] = cnt < MAXDEG ? cnt : MAXDEG;
}

__global__ void k_init(const float* __restrict__ vh0i, const float* __restrict__ vh1i,
                       const float* __restrict__ chi)
{
    int i = blockIdx.x * blockDim.x + threadIdx.x;
    if (i < VND) {
        g_vh0[0][i] = vh0i[i];
        g_vh1[0][i] = vh1i[i];
        g_vc0[0][i] = 0.f;
        g_vc1[0][i] = 0.f;
    }
    if (i < CDD) { g_ch[0][i] = chi[i]; g_cc[0][i] = 0.f; }
}

// ---------------- weight image build (once per replay) -------------------
__global__ void k_prepw(const float* __restrict__ Wih0, const float* __restrict__ Whh0,
                        const float* __restrict__ Wih1, const float* __restrict__ Whh1)
{
    int idx = blockIdx.x * blockDim.x + threadIdx.x;   // 0..65535
    if (idx >= 65536) return;
    int mat = idx >> 15;
    int rem = idx & 32767;
    int k = rem >> 8;
    int n = rem & 255;
    float v;
    if (mat == 0) v = (k < 64) ? Wih1[k * 256 + n]        : Whh1[(k - 64) * 256 + n];
    else          v = (k < 64) ? Wih0[(64 + k) * 256 + n] : Whh0[(k - 64) * 256 + n];
    __nv_bfloat16 h = __float2bfloat16(v);
    __nv_bfloat16 l = __float2bfloat16(v - __bfloat162float(h));
    if (mat == 0) { g_W1hi[k * 256 + n] = h; g_W1lo[k * 256 + n] = l; }
    else          { g_W0hi[k * 256 + n] = h; g_W0lo[k * 256 + n] = l; }
}

// stage two fp32 sources as bf16 hi/lo A tile [64][LDA]
__device__ __forceinline__ void stage_a(__nv_bfloat16* Ah, __nv_bfloat16* Al, int tid,
                                        const float* src0, const float* src1)
{
    for (int i = tid; i < 4096; i += 256) {
        int r = i >> 6, k = (i & 63) * 2;
        float2 v = (k < 64) ? *(const float2*)(src0 + r * 64 + k)
                            : *(const float2*)(src1 + r * 64 + k - 64);
        __nv_bfloat162 h2 = __float22bfloat162_rn(v);
        float2 bk; bk.x = __bfloat162float(h2.x); bk.y = __bfloat162float(h2.y);
        float2 lo; lo.x = v.x - bk.x; lo.y = v.y - bk.y;
        __nv_bfloat162 l2 = __float22bfloat162_rn(lo);
        *(__nv_bfloat162*)(Ah + r * LDA + k) = h2;
        *(__nv_bfloat162*)(Al + r * LDA + k) = l2;
    }
}

// wmma GEMM: gates[64][LDG_] = A[64][128](smem) @ W[128][256](global), 3-term hi/lo
__device__ __forceinline__ void wmma_gemm(const __nv_bfloat16* Ah, const __nv_bfloat16* Al,
                                          const __nv_bfloat16* __restrict__ Wh,
                                          const __nv_bfloat16* __restrict__ Wl,
                                          float* gates, int w)
{
    int rowtile = w >> 1;
    wmma::fragment<wmma::matrix_a, 16, 16, 16, __nv_bfloat16, wmma::row_major> aHi, aLo;
    wmma::fragment<wmma::matrix_b, 16, 16, 16, __nv_bfloat16, wmma::row_major> bHi, bLo;
    #pragma unroll
    for (int cg = 0; cg < 2; cg++) {
        int colbase = (w & 1) * 128 + cg * 64;
        wmma::fragment<wmma::accumulator, 16, 16, 16, float> acc[4];
        #pragma unroll
        for (int ct = 0; ct < 4; ct++) wmma::fill_fragment(acc[ct], 0.0f);
        #pragma unroll
        for (int k = 0; k < 8; k++) {
            wmma::load_matrix_sync(aHi, Ah + rowtile * 16 * LDA + k * 16, LDA);
            wmma::load_matrix_sync(aLo, Al + rowtile * 16 * LDA + k * 16, LDA);
            #pragma unroll
            for (int ct = 0; ct < 4; ct++) {
                const __nv_bfloat16* bp = Wh + (k * 16) * 256 + colbase + ct * 16;
                const __nv_bfloat16* bq = Wl + (k * 16) * 256 + colbase + ct * 16;
                wmma::load_matrix_sync(bHi, bp, 256);
                wmma::load_matrix_sync(bLo, bq, 256);
                wmma::mma_sync(acc[ct], aHi, bHi, acc[ct]);
                wmma::mma_sync(acc[ct], aHi, bLo, acc[ct]);
                wmma::mma_sync(acc[ct], aLo, bHi, acc[ct]);
            }
        }
        #pragma unroll
        for (int ct = 0; ct < 4; ct++)
            wmma::store_matrix_sync(gates + rowtile * 16 * LDG_ + colbase + ct * 16,
                                    acc[ct], LDG_, wmma::mem_row_major);
    }
}

// ---------------- kernel GM: mv gather + vmsg MLP (reads vh1_old only) ---
// grid = 512 (64 batches x 8 tiles of 64 rows), 256 threads, 2 blocks/SM
constexpr int SMEM_GM = 24064 * 4;
constexpr int GM_X1 = 0, GM_W1 = 4352, GM_W2 = 10752, GM_H = 17152, GM_R = 23808;

__global__ __launch_bounds__(256, 2)
void k_gm(int old, const float* __restrict__ vW1, const float* __restrict__ vb1,
          const float* __restrict__ vW2, const float* __restrict__ vb2)
{
    extern __shared__ float smf[];
    const int tid = threadIdx.x;
    const int lane = tid & 31, w = tid >> 5;
    const int b = blockIdx.x >> 3;
    const int tile = blockIdx.x & 7;
    const int row0 = tile * 64;
    const size_t base = ((size_t)b * N_ + row0) * D_;

    // stage X1 (vh1_old rows) + W1 + W2
    {
        const float4* px = (const float4*)(g_vh1[old] + base);
        for (int i = tid; i < 1024; i += 256) {
            int r = i >> 4, q = i & 15;
            *(float4*)(smf + GM_X1 + r * 68 + q * 4) = px[i];
        }
        const float4* p1 = (const float4*)vW1;
        const float4* p2 = (const float4*)vW2;
        for (int i = tid; i < 1600; i += 256) {
            ((float4*)(smf + GM_W1))[i] = p1[i];
            ((float4*)(smf + GM_W2))[i] = p2[i];
        }
    }

    // sparse mv gather (overlaps staging latency; independent of smem)
    {
        const float* vh1b = g_vh1[old] + (size_t)b * N_ * D_;
        for (int r = w; r < 64; r += 8) {
            int n = row0 + r;
            int deg = g_deg[b * N_ + n];
            const unsigned short* nb = g_nbr + ((size_t)(b * N_ + n)) * MAXDEG;
            float a0 = 0.f, a1 = 0.f, b0 = 0.f, b1 = 0.f, c0 = 0.f, c1 = 0.f, d0 = 0.f, d1 = 0.f;
            int k = 0;
            for (; k + 4 <= deg; k += 4) {
                float2 v0 = *(const float2*)(vh1b + (size_t)nb[k]     * D_ + lane * 2);
                float2 v1 = *(const float2*)(vh1b + (size_t)nb[k + 1] * D_ + lane * 2);
                float2 v2 = *(const float2*)(vh1b + (size_t)nb[k + 2] * D_ + lane * 2);
                float2 v3 = *(const float2*)(vh1b + (size_t)nb[k + 3] * D_ + lane * 2);
                a0 += v0.x; a1 += v0.y; b0 += v1.x; b1 += v1.y;
                c0 += v2.x; c1 += v2.y; d0 += v3.x; d1 += v3.y;
            }
            for (; k < deg; k++) {
                float2 v = *(const float2*)(vh1b + (size_t)nb[k] * D_ + lane * 2);
                a0 += v.x; a1 += v.y;
            }
            *((float2*)(g_mv + ((size_t)b * N_ + n) * D_) + lane) =
                make_float2(a0 + b0 + c0 + d0, a1 + b1 + c1 + d1);
        }
    }
    __syncthreads();

    // vmsg MLP layer 1: quad-blocked — thread computes 4 consecutive h
    {
        float* X1 = smf + GM_X1;
        float* W1 = smf + GM_W1;
        float* H  = smf + GM_H;
        for (int idx = tid; idx < 1600; idx += 256) {
            int r = idx / 25, q = idx - r * 25;     // h = 4q..4q+3
            float ax = 0.f, ay = 0.f, az = 0.f, aw = 0.f;
            #pragma unroll 4
            for (int k = 0; k < 64; k++) {
                float x = X1[r * 68 + k];
                float4 wv = *(const float4*)(W1 + k * 100 + q * 4);
                ax = fmaf(x, wv.x, ax);
                ay = fmaf(x, wv.y, ay);
                az = fmaf(x, wv.z, az);
                aw = fmaf(x, wv.w, aw);
            }
            int h = q * 4;
            H[r * 104 + h + 0] = fmaxf(ax + vb1[h + 0], 0.f);
            H[r * 104 + h + 1] = fmaxf(ay + vb1[h + 1], 0.f);
            H[r * 104 + h + 2] = fmaxf(az + vb1[h + 2], 0.f);
            H[r * 104 + h + 3] = fmaxf(aw + vb1[h + 3], 0.f);
        }
    }
    __syncthreads();
    // layer 2 quad-blocked: 1024 units = 64 rows x 16 quads of d
    {
        float* W2 = smf + GM_W2;
        float* H  = smf + GM_H;
        float* V  = smf + GM_X1;   // overlay over X1 (not read in this phase)
        for (int idx = tid; idx < 1024; idx += 256) {
            int r = idx >> 4, q = idx & 15;         // d = 4q..4q+3
            float ax = 0.f, ay = 0.f, az = 0.f, aw = 0.f;
            #pragma unroll 4
            for (int k = 0; k < 100; k++) {
                float x = H[r * 104 + k];
                float4 wv = *(const float4*)(W2 + k * 64 + q * 4);
                ax = fmaf(x, wv.x, ax);
                ay = fmaf(x, wv.y, ay);
                az = fmaf(x, wv.z, az);
                aw = fmaf(x, wv.w, aw);
            }
            int d = q * 4;
            V[r * 68 + d + 0] = fmaxf(ax + vb2[d + 0], 0.f);
            V[r * 68 + d + 1] = fmaxf(ay + vb2[d + 1], 0.f);
            V[r * 68 + d + 2] = fmaxf(az + vb2[d + 2], 0.f);
            V[r * 68 + d + 3] = fmaxf(aw + vb2[d + 3], 0.f);
        }
    }
    __syncthreads();
    {
        float* V = smf + GM_X1;
        float* R = smf + GM_R;
        int q = tid >> 6, d = tid & 63;
        float s = 0.f;
        #pragma unroll
        for (int r = 0; r < 16; r++) s += V[(q * 16 + r) * 68 + d];
        R[q * 64 + d] = s;
        __syncthreads();
        if (tid < 64)
            g_vpart[(b * 8 + tile) * 64 + tid] =
                R[tid] + R[64 + tid] + R[128 + tid] + R[192 + tid];
    }
}

// ---------------- smem layout for A2/B -----------------------------------
constexpr int SMEM_AB = 26112 * 4;   // A tiles (8704 f) + gates (17408 f)
constexpr int F_GATES = 8704;

// ---------------- kernel A2: LSTM1 (stage + wmma + activation) -----------
__global__ __launch_bounds__(256, 2)
void k_stepA2(int old, const float* __restrict__ bih1, const float* __restrict__ bhh1)
{
    extern __shared__ float smf[];
    __nv_bfloat16* Ah = (__nv_bfloat16*)smf;
    __nv_bfloat16* Al = Ah + 64 * LDA;
    float* gates = smf + F_GATES;
    __shared__ float bsum[256];
    const int tid = threadIdx.x;
    const int w = tid >> 5;
    const int b = blockIdx.x >> 3;
    const int tile = blockIdx.x & 7;
    const int row0 = tile * 64;
    const size_t base = ((size_t)b * N_ + row0) * D_;
    const int nw = 1 - old;

    bsum[tid] = bih1[tid] + bhh1[tid];
    stage_a(Ah, Al, tid, g_vh0[old] + base, g_vh1[old] + base);
    __syncthreads();

    wmma_gemm(Ah, Al, g_W1hi, g_W1lo, gates, w);
    __syncthreads();

    {
        const float* vc1o = g_vc1[old] + base;
        float* vh1n = g_vh1[nw] + base;
        float* vc1n = g_vc1[nw] + base;
        for (int i = tid; i < 4096; i += 256) {
            int r = i >> 6, d = i & 63;
            float gi = gates[r * LDG_ + d]       + bsum[d];
            float gf = gates[r * LDG_ + 64 + d]  + bsum[64 + d];
            float gg = gates[r * LDG_ + 128 + d] + bsum[128 + d];
            float go = gates[r * LDG_ + 192 + d] + bsum[192 + d];
            float c2 = sigf(gf) * vc1o[i] + sigf(gi) * tanhfast(gg);
            vc1n[i] = c2;
            vh1n[i] = sigf(go) * tanhfast(c2);
        }
    }
}

// ---------------- kernel B: LSTM0 (stage + wmma + activation) ------------
__global__ __launch_bounds__(256, 2)
void k_stepB(int old)
{
    extern __shared__ float smf[];
    __nv_bfloat16* Ah = (__nv_bfloat16*)smf;
    __nv_bfloat16* Al = Ah + 64 * LDA;
    float* gates = smf + F_GATES;
    __shared__ float bsum[256];
    const int tid = threadIdx.x;
    const int w = tid >> 5;
    const int b = blockIdx.x >> 3;
    const int tile = blockIdx.x & 7;
    const int row0 = tile * 64;
    const size_t base = ((size_t)b * N_ + row0) * D_;
    const int nw = 1 - old;

    bsum[tid] = g_mcg[b * 256 + tid];
    stage_a(Ah, Al, tid, g_mv + base, g_vh0[old] + base);
    __syncthreads();

    wmma_gemm(Ah, Al, g_W0hi, g_W0lo, gates, w);
    __syncthreads();

    {
        const float* vc0o = g_vc0[old] + base;
        float* vh0n = g_vh0[nw] + base;
        float* vc0n = g_vc0[nw] + base;
        for (int i = tid; i < 4096; i += 256) {
            int r = i >> 6, d = i & 63;
            float gi = gates[r * LDG_ + d]       + bsum[d];
            float gf = gates[r * LDG_ + 64 + d]  + bsum[64 + d];
            float gg = gates[r * LDG_ + 128 + d] + bsum[128 + d];
            float go = gates[r * LDG_ + 192 + d] + bsum[192 + d];
            float c2 = sigf(gf) * vc0o[i] + sigf(gi) * tanhfast(gg);
            vc0n[i] = c2;
            vh0n[i] = sigf(go) * tanhfast(c2);
        }
    }
}

// ---------------- kernel C: color-side; grid = 64, 256 threads -----------
__global__ __launch_bounds__(256, 1)
void k_stepC(int old, const int* __restrict__ n_colors,
             const float* __restrict__ cW1, const float* __restrict__ cb1,
             const float* __restrict__ cW2, const float* __restrict__ cb2,
             const float* __restrict__ Wih0, const float* __restrict__ bih0,
             const float* __restrict__ bhh0,
             const float* __restrict__ Wihc, const float* __restrict__ Whhc,
             const float* __restrict__ bihc, const float* __restrict__ bhhc)
{
    extern __shared__ float sm[];
    float* vsum  = sm;                // 64
    float* chs   = vsum + 64;         // 1024
    float* cW1s  = chs + 1024;        // 6400
    float* cW2s  = cW1s + 6400;       // 6400
    float* hid   = cW2s + 6400;       // 1664
    float* cmsgs = hid + 1664;        // 1024
    float* mcv   = cmsgs + 1024;      // 64
    float* xps   = mcv + 64;          // 256
    float* gcs   = xps + 256;         // 4160

    const int tid = threadIdx.x;
    const int b = blockIdx.x;
    const int nw = 1 - old;
    const int nc = n_colors[b];

    if (tid < 64) {
        float s = 0.f;
        #pragma unroll
        for (int blk = 0; blk < 8; blk++) s += g_vpart[(b * 8 + blk) * 64 + tid];
        vsum[tid] = s;
    }
    {
        const float4* pc = (const float4*)(g_ch[old] + b * 1024);
        for (int i = tid; i < 256; i += 256) ((float4*)chs)[i] = pc[i];
        const float4* p1 = (const float4*)cW1;
        const float4* p2 = (const float4*)cW2;
        for (int i = tid; i < 1600; i += 256) {
            ((float4*)cW1s)[i] = p1[i];
            ((float4*)cW2s)[i] = p2[i];
        }
    }
    __syncthreads();

    // layer 1 quad-blocked: 400 units = 16 rows x 25 quads
    for (int idx = tid; idx < 400; idx += 256) {
        int c = idx / 25, q = idx - c * 25;
        float ax = 0.f, ay = 0.f, az = 0.f, aw = 0.f;
        #pragma unroll 4
        for (int k = 0; k < 64; k++) {
            float x = chs[c * 64 + k];
            float4 wv = *(const float4*)(cW1s + k * 100 + q * 4);
            ax = fmaf(x, wv.x, ax);
            ay = fmaf(x, wv.y, ay);
            az = fmaf(x, wv.z, az);
            aw = fmaf(x, wv.w, aw);
        }
        int h = q * 4;
        hid[c * 104 + h + 0] = fmaxf(ax + cb1[h + 0], 0.f);
        hid[c * 104 + h + 1] = fmaxf(ay + cb1[h + 1], 0.f);
        hid[c * 104 + h + 2] = fmaxf(az + cb1[h + 2], 0.f);
        hid[c * 104 + h + 3] = fmaxf(aw + cb1[h + 3], 0.f);
    }
    __syncthreads();
    // layer 2 quad-blocked: 256 units = 16 rows x 16 quads
    {
        int c = tid >> 4, q = tid & 15;
        float ax = 0.f, ay = 0.f, az = 0.f, aw = 0.f;
        #pragma unroll 4
        for (int k = 0; k < 100; k++) {
            float x = hid[c * 104 + k];
            float4 wv = *(const float4*)(cW2s + k * 64 + q * 4);
            ax = fmaf(x, wv.x, ax);
            ay = fmaf(x, wv.y, ay);
            az = fmaf(x, wv.z, az);
            aw = fmaf(x, wv.w, aw);
        }
        int d = q * 4;
        cmsgs[c * 64 + d + 0] = fmaxf(ax + cb2[d + 0], 0.f);
        cmsgs[c * 64 + d + 1] = fmaxf(ay + cb2[d + 1], 0.f);
        cmsgs[c * 64 + d + 2] = fmaxf(az + cb2[d + 2], 0.f);
        cmsgs[c * 64 + d + 3] = fmaxf(aw + cb2[d + 3], 0.f);
    }
    __syncthreads();
    if (tid < 64) {
        float s = 0.f;
        for (int c = 0; c < nc; c++) s += cmsgs[c * 64 + tid];
        mcv[tid] = s;
    }
    __syncthreads();
    {
        int g = tid;
        float a0 = bih0[g] + bhh0[g], a1 = 0.f;
        float x0 = 0.f, x1 = 0.f;
        #pragma unroll 8
        for (int d = 0; d < 64; d += 2) {
            a0 = fmaf(mcv[d],      Wih0[d * 256 + g],       a0);
            a1 = fmaf(mcv[d + 1],  Wih0[(d + 1) * 256 + g], a1);
            x0 = fmaf(vsum[d],     Wihc[d * 256 + g],       x0);
            x1 = fmaf(vsum[d + 1], Wihc[(d + 1) * 256 + g], x1);
        }
        g_mcg[b * 256 + g] = a0 + a1;
        xps[g] = x0 + x1;
    }
    __syncthreads();
    {
        int c = tid >> 4, seg = (tid & 15) * 16;
        float a[16];
        #pragma unroll
        for (int i = 0; i < 16; i++) a[i] = 0.f;
        for (int k = 0; k < 64; k++) {
            float x = chs[c * 64 + k];
            const float4* wrow = (const float4*)(Whhc + k * 256 + seg);
            float4 w0 = wrow[0], w1 = wrow[1], w2 = wrow[2], w3 = wrow[3];
            a[0]  = fmaf(x, w0.x, a[0]);  a[1]  = fmaf(x, w0.y, a[1]);
            a[2]  = fmaf(x, w0.z, a[2]);  a[3]  = fmaf(x, w0.w, a[3]);
            a[4]  = fmaf(x, w1.x, a[4]);  a[5]  = fmaf(x, w1.y, a[5]);
            a[6]  = fmaf(x, w1.z, a[6]);  a[7]  = fmaf(x, w1.w, a[7]);
            a[8]  = fmaf(x, w2.x, a[8]);  a[9]  = fmaf(x, w2.y, a[9]);
            a[10] = fmaf(x, w2.z, a[10]); a[11] = fmaf(x, w2.w, a[11]);
            a[12] = fmaf(x, w3.x, a[12]); a[13] = fmaf(x, w3.y, a[13]);
            a[14] = fmaf(x, w3.z, a[14]); a[15] = fmaf(x, w3.w, a[15]);
        }
        float mk = (c < nc) ? 1.f : 0.f;
        #pragma unroll
        for (int i = 0; i < 16; i++) {
            int g = seg + i;
            gcs[c * 260 + g] = a[i] + mk * xps[g] + bihc[g] + bhhc[g];
        }
    }
    __syncthreads();
    {
        const float* cco = g_cc[old] + b * 1024;
        float* chn = g_ch[nw] + b * 1024;
        float* ccn = g_cc[nw] + b * 1024;
        for (int i = tid; i < 1024; i += 256) {
            int c = i >> 6, d = i & 63;
            float gi  = gcs[c * 260 + d];
            float gf  = gcs[c * 260 + 64 + d];
            float gg2 = gcs[c * 260 + 128 + d];
            float go  = gcs[c * 260 + 192 + d];
            float c2 = sigf(gf) * cco[i] + sigf(gi) * tanhfast(gg2);
            ccn[i] = c2;
            chn[i] = sigf(go) * tanhfast(c2);
        }
    }
}

// ---------------- vote head ----------------------------------------------
__global__ void k_vote(const float* __restrict__ W1, const float* __restrict__ b1,
                       const float* __restrict__ W2, const float* __restrict__ b2,
                       float* __restrict__ out)
{
    __shared__ float w1s[64 * 16];
    __shared__ float w2s[16];
    __shared__ float red[256];
    const int tid = threadIdx.x, b = blockIdx.x;
    for (int i = tid; i < 64 * 16; i += 256) w1s[i] = W1[i];
    if (tid < 16) w2s[tid] = W2[tid];
    __syncthreads();

    float acc = 0.f;
    for (int r = tid; r < N_; r += 256) {
        const float* x = g_vh1[0] + ((size_t)b * N_ + r) * D_;
        float h[16];
        #pragma unroll
        for (int j = 0; j < 16; j++) h[j] = b1[j];
        for (int k = 0; k < 64; k++) {
            float xv = x[k];
            #pragma unroll
            for (int j = 0; j < 16; j++) h[j] = fmaf(xv, w1s[k * 16 + j], h[j]);
        }
        float v = b2[0];
        #pragma unroll
        for (int j = 0; j < 16; j++) v += sigf(h[j]) * w2s[j];
        acc += sigf(v);
    }
    red[tid] = acc;
    __syncthreads();
    for (int s = 128; s > 0; s >>= 1) {
        if (tid < s) red[tid] += red[tid + s];
        __syncthreads();
    }
    if (tid == 0) out[b] = sigf(red[0] / (float)N_);
}

// ---------------- launch -------------------------------------------------
extern "C" void kernel_launch(void* const* d_in, const int* in_sizes, int n_in,
                              void* d_out, int out_size)
{
    const float* Mvv      = (const float*)d_in[0];
    const int*   n_colors = (const int*)d_in[1];
    const float* vh0i     = (const float*)d_in[2];
    const float* vh1i     = (const float*)d_in[3];
    const float* chi      = (const float*)d_in[4];
    const float* Wih0 = (const float*)d_in[5];
    const float* Whh0 = (const float*)d_in[6];
    const float* bih0 = (const float*)d_in[7];
    const float* bhh0 = (const float*)d_in[8];
    const float* Wih1 = (const float*)d_in[9];
    const float* Whh1 = (const float*)d_in[10];
    const float* bih1 = (const float*)d_in[11];
    const float* bhh1 = (const float*)d_in[12];
    const float* Wihc = (const float*)d_in[13];
    const float* Whhc = (const float*)d_in[14];
    const float* bihc = (const float*)d_in[15];
    const float* bhhc = (const float*)d_in[16];
    const float* cW1 = (const float*)d_in[17];
    const float* cb1 = (const float*)d_in[18];
    const float* cW2 = (const float*)d_in[19];
    const float* cb2 = (const float*)d_in[20];
    const float* vW1 = (const float*)d_in[21];
    const float* vb1 = (const float*)d_in[22];
    const float* vW2 = (const float*)d_in[23];
    const float* vb2 = (const float*)d_in[24];
    const float* voteW1 = (const float*)d_in[25];
    const float* voteb1 = (const float*)d_in[26];
    const float* voteW2 = (const float*)d_in[27];
    const float* voteb2 = (const float*)d_in[28];
    float* out = (float*)d_out;

    const int SMEM_C = 21056 * 4;
    cudaFuncSetAttribute(k_gm,     cudaFuncAttributeMaxDynamicSharedMemorySize, SMEM_GM);
    cudaFuncSetAttribute(k_stepA2, cudaFuncAttributeMaxDynamicSharedMemorySize, SMEM_AB);
    cudaFuncSetAttribute(k_stepB,  cudaFuncAttributeMaxDynamicSharedMemorySize, SMEM_AB);
    cudaFuncSetAttribute(k_stepC,  cudaFuncAttributeMaxDynamicSharedMemorySize, SMEM_C);

    k_adj<<<(B_ * N_ * 32 + 255) / 256, 256>>>(Mvv);
    k_init<<<(VND + 255) / 256, 256>>>(vh0i, vh1i, chi);
    k_prepw<<<256, 256>>>(Wih0, Whh0, Wih1, Whh1);

    for (int t = 0; t < T_; t++) {
        int old = t & 1;
        k_gm<<<512, 256, SMEM_GM>>>(old, vW1, vb1, vW2, vb2);
        k_stepC<<<64, 256, SMEM_C>>>(old, n_colors, cW1, cb1, cW2, cb2,
                                     Wih0, bih0, bhh0, Wihc, Whhc, bihc, bhhc);
        k_stepA2<<<512, 256, SMEM_AB>>>(old, bih1, bhh1);
        k_stepB<<<512, 256, SMEM_AB>>>(old);
    }
    k_vote<<<B_, 256>>>(voteW1, voteb1, voteW2, voteb2, out);
}

// round 15
// speedup vs baseline: 1.2910x; 1.1696x over previous
#include <cuda_runtime.h>
#include <cuda_bf16.h>
#include <mma.h>
#include <cstdint>
#include <cstddef>
#include <math.h>

using namespace nvcuda;

constexpr int B_ = 64, N_ = 512, C_ = 16, D_ = 64, T_ = 32;
constexpr int VND = B_ * N_ * D_;
constexpr int CDD = B_ * C_ * D_;
constexpr int MAXDEG = 160;

constexpr int LDA = 136;   // smem A tile [64][LDA] bf16 (bank-spread padding)
constexpr int LDG_ = 272;  // gates [64][LDG_] f32

// ---------------- state (device globals; allocation-free) ----------------
__device__ float g_vh0[2][VND];
__device__ float g_vh1[2][VND];
__device__ float g_vc0[2][VND];
__device__ float g_vc1[2][VND];
__device__ float g_ch[2][CDD];
__device__ float g_cc[2][CDD];
__device__ float g_mv[VND];
__device__ float g_vpart[B_ * 8 * 64];
__device__ float g_mcg[B_ * 256];
__device__ unsigned short g_nbr[(size_t)B_ * N_ * MAXDEG];
__device__ int g_deg[B_ * N_];
__device__ __nv_bfloat16 g_W1hi[32768], g_W1lo[32768];
__device__ __nv_bfloat16 g_W0hi[32768], g_W0lo[32768];

__device__ __forceinline__ float sigf(float x)     { return 1.0f / (1.0f + __expf(-x)); }
__device__ __forceinline__ float tanhfast(float x) { return 2.0f / (1.0f + __expf(-2.0f * x)) - 1.0f; }

// ---------------- adjacency build ----------------
__global__ void k_adj(const float* __restrict__ Mvv)
{
    int gw = (blockIdx.x * blockDim.x + threadIdx.x) >> 5;
    int lane = threadIdx.x & 31;
    if (gw >= B_ * N_) return;
    const float* row = Mvv + (size_t)gw * N_;
    unsigned short* outp = g_nbr + (size_t)gw * MAXDEG;
    int cnt = 0;
    for (int base = 0; base < N_; base += 32) {
        float v = row[base + lane];
        unsigned m = __ballot_sync(0xffffffffu, v != 0.0f);
        if (v != 0.0f) {
            int pos = cnt + __popc(m & ((1u << lane) - 1u));
            if (pos < MAXDEG) outp[pos] = (unsigned short)(base + lane);
        }
        cnt += __popc(m);
    }
    if (lane == 0) g_deg[gw] = cnt < MAXDEG ? cnt : MAXDEG;
}

__global__ void k_init(const float* __restrict__ vh0i, const float* __restrict__ vh1i,
                       const float* __restrict__ chi)
{
    int i = blockIdx.x * blockDim.x + threadIdx.x;
    if (i < VND) {
        g_vh0[0][i] = vh0i[i];
        g_vh1[0][i] = vh1i[i];
        g_vc0[0][i] = 0.f;
        g_vc1[0][i] = 0.f;
    }
    if (i < CDD) { g_ch[0][i] = chi[i]; g_cc[0][i] = 0.f; }
}

// ---------------- weight image build (once per replay) -------------------
__global__ void k_prepw(const float* __restrict__ Wih0, const float* __restrict__ Whh0,
                        const float* __restrict__ Wih1, const float* __restrict__ Whh1)
{
    int idx = blockIdx.x * blockDim.x + threadIdx.x;
    if (idx >= 65536) return;
    int mat = idx >> 15;
    int rem = idx & 32767;
    int k = rem >> 8;
    int n = rem & 255;
    float v;
    if (mat == 0) v = (k < 64) ? Wih1[k * 256 + n]        : Whh1[(k - 64) * 256 + n];
    else          v = (k < 64) ? Wih0[(64 + k) * 256 + n] : Whh0[(k - 64) * 256 + n];
    __nv_bfloat16 h = __float2bfloat16(v);
    __nv_bfloat16 l = __float2bfloat16(v - __bfloat162float(h));
    if (mat == 0) { g_W1hi[k * 256 + n] = h; g_W1lo[k * 256 + n] = l; }
    else          { g_W0hi[k * 256 + n] = h; g_W0lo[k * 256 + n] = l; }
}

// stage two fp32 sources as bf16 hi/lo A tile [64][LDA]
__device__ __forceinline__ void stage_a(__nv_bfloat16* Ah, __nv_bfloat16* Al, int tid,
                                        const float* src0, const float* src1)
{
    for (int i = tid; i < 4096; i += 256) {
        int r = i >> 6, k = (i & 63) * 2;
        float2 v = (k < 64) ? *(const float2*)(src0 + r * 64 + k)
                            : *(const float2*)(src1 + r * 64 + k - 64);
        __nv_bfloat162 h2 = __float22bfloat162_rn(v);
        float2 bk; bk.x = __bfloat162float(h2.x); bk.y = __bfloat162float(h2.y);
        float2 lo; lo.x = v.x - bk.x; lo.y = v.y - bk.y;
        __nv_bfloat162 l2 = __float22bfloat162_rn(lo);
        *(__nv_bfloat162*)(Ah + r * LDA + k) = h2;
        *(__nv_bfloat162*)(Al + r * LDA + k) = l2;
    }
}

// wmma GEMM: gates[64][LDG_] = A[64][128](smem) @ W[128][256](global), 3-term hi/lo
__device__ __forceinline__ void wmma_gemm(const __nv_bfloat16* Ah, const __nv_bfloat16* Al,
                                          const __nv_bfloat16* __restrict__ Wh,
                                          const __nv_bfloat16* __restrict__ Wl,
                                          float* gates, int w)
{
    int rowtile = w >> 1;
    wmma::fragment<wmma::matrix_a, 16, 16, 16, __nv_bfloat16, wmma::row_major> aHi, aLo;
    wmma::fragment<wmma::matrix_b, 16, 16, 16, __nv_bfloat16, wmma::row_major> bHi, bLo;
    #pragma unroll
    for (int cg = 0; cg < 2; cg++) {
        int colbase = (w & 1) * 128 + cg * 64;
        wmma::fragment<wmma::accumulator, 16, 16, 16, float> acc[4];
        #pragma unroll
        for (int ct = 0; ct < 4; ct++) wmma::fill_fragment(acc[ct], 0.0f);
        #pragma unroll
        for (int k = 0; k < 8; k++) {
            wmma::load_matrix_sync(aHi, Ah + rowtile * 16 * LDA + k * 16, LDA);
            wmma::load_matrix_sync(aLo, Al + rowtile * 16 * LDA + k * 16, LDA);
            #pragma unroll
            for (int ct = 0; ct < 4; ct++) {
                const __nv_bfloat16* bp = Wh + (k * 16) * 256 + colbase + ct * 16;
                const __nv_bfloat16* bq = Wl + (k * 16) * 256 + colbase + ct * 16;
                wmma::load_matrix_sync(bHi, bp, 256);
                wmma::load_matrix_sync(bLo, bq, 256);
                wmma::mma_sync(acc[ct], aHi, bHi, acc[ct]);
                wmma::mma_sync(acc[ct], aHi, bLo, acc[ct]);
                wmma::mma_sync(acc[ct], aLo, bHi, acc[ct]);
            }
        }
        #pragma unroll
        for (int ct = 0; ct < 4; ct++)
            wmma::store_matrix_sync(gates + rowtile * 16 * LDG_ + colbase + ct * 16,
                                    acc[ct], LDG_, wmma::mem_row_major);
    }
}

// shared LSTM epilogue (gates in smem -> new h/c in global)
__device__ __forceinline__ void lstm_act(const float* gates, const float* bsum,
                                         const float* c_old, float* h_new, float* c_new,
                                         int tid)
{
    for (int i = tid; i < 4096; i += 256) {
        int r = i >> 6, d = i & 63;
        float gi = gates[r * LDG_ + d]       + bsum[d];
        float gf = gates[r * LDG_ + 64 + d]  + bsum[64 + d];
        float gg = gates[r * LDG_ + 128 + d] + bsum[128 + d];
        float go = gates[r * LDG_ + 192 + d] + bsum[192 + d];
        float c2 = sigf(gf) * c_old[i] + sigf(gi) * tanhfast(gg);
        c_new[i] = c2;
        h_new[i] = sigf(go) * tanhfast(c2);
    }
}

// ================= kernel FRONT: gm (512 blocks) + C1/mcg (64 blocks) ====
// smem = SMEM_GM (96,256 B), 256 threads, 2 blocks/SM
constexpr int SMEM_GM = 24064 * 4;
constexpr int GM_X1 = 0, GM_W1 = 4352, GM_W2 = 10752, GM_H = 17152, GM_R = 23808;

__global__ __launch_bounds__(256, 2)
void k_front(int old, const float* __restrict__ vW1, const float* __restrict__ vb1,
             const float* __restrict__ vW2, const float* __restrict__ vb2,
             const int* __restrict__ n_colors,
             const float* __restrict__ cW1, const float* __restrict__ cb1,
             const float* __restrict__ cW2, const float* __restrict__ cb2,
             const float* __restrict__ Wih0, const float* __restrict__ bih0,
             const float* __restrict__ bhh0)
{
    extern __shared__ float smf[];
    const int tid = threadIdx.x;

    if (blockIdx.x < 512) {
        // ----- gm role: mv gather + vmsg MLP -----
        const int lane = tid & 31, w = tid >> 5;
        const int b = blockIdx.x >> 3;
        const int tile = blockIdx.x & 7;
        const int row0 = tile * 64;
        const size_t base = ((size_t)b * N_ + row0) * D_;

        {
            const float4* px = (const float4*)(g_vh1[old] + base);
            for (int i = tid; i < 1024; i += 256) {
                int r = i >> 4, q = i & 15;
                *(float4*)(smf + GM_X1 + r * 68 + q * 4) = px[i];
            }
            const float4* p1 = (const float4*)vW1;
            const float4* p2 = (const float4*)vW2;
            for (int i = tid; i < 1600; i += 256) {
                ((float4*)(smf + GM_W1))[i] = p1[i];
                ((float4*)(smf + GM_W2))[i] = p2[i];
            }
        }
        {
            const float* vh1b = g_vh1[old] + (size_t)b * N_ * D_;
            for (int r = w; r < 64; r += 8) {
                int n = row0 + r;
                int deg = g_deg[b * N_ + n];
                const unsigned short* nb = g_nbr + ((size_t)(b * N_ + n)) * MAXDEG;
                float a0 = 0.f, a1 = 0.f, b0 = 0.f, b1 = 0.f, c0 = 0.f, c1 = 0.f, d0 = 0.f, d1 = 0.f;
                int k = 0;
                for (; k + 4 <= deg; k += 4) {
                    float2 v0 = *(const float2*)(vh1b + (size_t)nb[k]     * D_ + lane * 2);
                    float2 v1 = *(const float2*)(vh1b + (size_t)nb[k + 1] * D_ + lane * 2);
                    float2 v2 = *(const float2*)(vh1b + (size_t)nb[k + 2] * D_ + lane * 2);
                    float2 v3 = *(const float2*)(vh1b + (size_t)nb[k + 3] * D_ + lane * 2);
                    a0 += v0.x; a1 += v0.y; b0 += v1.x; b1 += v1.y;
                    c0 += v2.x; c1 += v2.y; d0 += v3.x; d1 += v3.y;
                }
                for (; k < deg; k++) {
                    float2 v = *(const float2*)(vh1b + (size_t)nb[k] * D_ + lane * 2);
                    a0 += v.x; a1 += v.y;
                }
                *((float2*)(g_mv + ((size_t)b * N_ + n) * D_) + lane) =
                    make_float2(a0 + b0 + c0 + d0, a1 + b1 + c1 + d1);
            }
        }
        __syncthreads();

        {
            float* X1 = smf + GM_X1;
            float* W1 = smf + GM_W1;
            float* H  = smf + GM_H;
            for (int idx = tid; idx < 1600; idx += 256) {
                int r = idx / 25, q = idx - r * 25;
                float ax = 0.f, ay = 0.f, az = 0.f, aw = 0.f;
                #pragma unroll 4
                for (int k = 0; k < 64; k++) {
                    float x = X1[r * 68 + k];
                    float4 wv = *(const float4*)(W1 + k * 100 + q * 4);
                    ax = fmaf(x, wv.x, ax);
                    ay = fmaf(x, wv.y, ay);
                    az = fmaf(x, wv.z, az);
                    aw = fmaf(x, wv.w, aw);
                }
                int h = q * 4;
                H[r * 104 + h + 0] = fmaxf(ax + vb1[h + 0], 0.f);
                H[r * 104 + h + 1] = fmaxf(ay + vb1[h + 1], 0.f);
                H[r * 104 + h + 2] = fmaxf(az + vb1[h + 2], 0.f);
                H[r * 104 + h + 3] = fmaxf(aw + vb1[h + 3], 0.f);
            }
        }
        __syncthreads();
        {
            float* W2 = smf + GM_W2;
            float* H  = smf + GM_H;
            float* V  = smf + GM_X1;
            for (int idx = tid; idx < 1024; idx += 256) {
                int r = idx >> 4, q = idx & 15;
                float ax = 0.f, ay = 0.f, az = 0.f, aw = 0.f;
                #pragma unroll 4
                for (int k = 0; k < 100; k++) {
                    float x = H[r * 104 + k];
                    float4 wv = *(const float4*)(W2 + k * 64 + q * 4);
                    ax = fmaf(x, wv.x, ax);
                    ay = fmaf(x, wv.y, ay);
                    az = fmaf(x, wv.z, az);
                    aw = fmaf(x, wv.w, aw);
                }
                int d = q * 4;
                V[r * 68 + d + 0] = fmaxf(ax + vb2[d + 0], 0.f);
                V[r * 68 + d + 1] = fmaxf(ay + vb2[d + 1], 0.f);
                V[r * 68 + d + 2] = fmaxf(az + vb2[d + 2], 0.f);
                V[r * 68 + d + 3] = fmaxf(aw + vb2[d + 3], 0.f);
            }
        }
        __syncthreads();
        {
            float* V = smf + GM_X1;
            float* R = smf + GM_R;
            int q = tid >> 6, d = tid & 63;
            float s = 0.f;
            #pragma unroll
            for (int r = 0; r < 16; r++) s += V[(q * 16 + r) * 68 + d];
            R[q * 64 + d] = s;
            __syncthreads();
            if (tid < 64)
                g_vpart[(b * 8 + tile) * 64 + tid] =
                    R[tid] + R[64 + tid] + R[128 + tid] + R[192 + tid];
        }
    } else {
        // ----- C1 role: cmsg MLP + mcg (needs only ch_old) -----
        const int b = blockIdx.x - 512;
        const int nc = n_colors[b];
        float* chs   = smf;            // 1024
        float* cW1s  = smf + 1024;     // 6400
        float* cW2s  = smf + 7424;     // 6400
        float* hid   = smf + 13824;    // 1664
        float* cmsgs = smf + 15488;    // 1024
        float* mcv   = smf + 16512;    // 64

        {
            const float4* pc = (const float4*)(g_ch[old] + b * 1024);
            for (int i = tid; i < 256; i += 256) ((float4*)chs)[i] = pc[i];
            const float4* p1 = (const float4*)cW1;
            const float4* p2 = (const float4*)cW2;
            for (int i = tid; i < 1600; i += 256) {
                ((float4*)cW1s)[i] = p1[i];
                ((float4*)cW2s)[i] = p2[i];
            }
        }
        __syncthreads();

        for (int idx = tid; idx < 400; idx += 256) {
            int c = idx / 25, q = idx - c * 25;
            float ax = 0.f, ay = 0.f, az = 0.f, aw = 0.f;
            #pragma unroll 4
            for (int k = 0; k < 64; k++) {
                float x = chs[c * 64 + k];
                float4 wv = *(const float4*)(cW1s + k * 100 + q * 4);
                ax = fmaf(x, wv.x, ax);
                ay = fmaf(x, wv.y, ay);
                az = fmaf(x, wv.z, az);
                aw = fmaf(x, wv.w, aw);
            }
            int h = q * 4;
            hid[c * 104 + h + 0] = fmaxf(ax + cb1[h + 0], 0.f);
            hid[c * 104 + h + 1] = fmaxf(ay + cb1[h + 1], 0.f);
            hid[c * 104 + h + 2] = fmaxf(az + cb1[h + 2], 0.f);
            hid[c * 104 + h + 3] = fmaxf(aw + cb1[h + 3], 0.f);
        }
        __syncthreads();
        {
            int c = tid >> 4, q = tid & 15;
            float ax = 0.f, ay = 0.f, az = 0.f, aw = 0.f;
            #pragma unroll 4
            for (int k = 0; k < 100; k++) {
                float x = hid[c * 104 + k];
                float4 wv = *(const float4*)(cW2s + k * 64 + q * 4);
                ax = fmaf(x, wv.x, ax);
                ay = fmaf(x, wv.y, ay);
                az = fmaf(x, wv.z, az);
                aw = fmaf(x, wv.w, aw);
            }
            int d = q * 4;
            cmsgs[c * 64 + d + 0] = fmaxf(ax + cb2[d + 0], 0.f);
            cmsgs[c * 64 + d + 1] = fmaxf(ay + cb2[d + 1], 0.f);
            cmsgs[c * 64 + d + 2] = fmaxf(az + cb2[d + 2], 0.f);
            cmsgs[c * 64 + d + 3] = fmaxf(aw + cb2[d + 3], 0.f);
        }
        __syncthreads();
        if (tid < 64) {
            float s = 0.f;
            for (int c = 0; c < nc; c++) s += cmsgs[c * 64 + tid];
            mcv[tid] = s;
        }
        __syncthreads();
        {
            int g = tid;
            float a0 = bih0[g] + bhh0[g], a1 = 0.f;
            #pragma unroll 8
            for (int d = 0; d < 64; d += 2) {
                a0 = fmaf(mcv[d],     Wih0[d * 256 + g],       a0);
                a1 = fmaf(mcv[d + 1], Wih0[(d + 1) * 256 + g], a1);
            }
            g_mcg[b * 256 + g] = a0 + a1;
        }
    }
}

// ================= kernel BACK: A2 (512) + B (512) + C2 (64) =============
constexpr int SMEM_AB = 26112 * 4;
constexpr int F_GATES = 8704;

__global__ __launch_bounds__(256, 2)
void k_back(int old, const float* __restrict__ bih1, const float* __restrict__ bhh1,
            const int* __restrict__ n_colors,
            const float* __restrict__ Wihc, const float* __restrict__ Whhc,
            const float* __restrict__ bihc, const float* __restrict__ bhhc)
{
    extern __shared__ float smf[];
    __shared__ float bsum[256];
    const int tid = threadIdx.x;
    const int bid = blockIdx.x;
    const int nw = 1 - old;

    if (bid < 1024) {
        // ----- A2 / B roles: stage + wmma + LSTM activation -----
        const bool isA = (bid < 512);
        const int lb = isA ? bid : bid - 512;
        const int b = lb >> 3;
        const int tile = lb & 7;
        const int row0 = tile * 64;
        const size_t base = ((size_t)b * N_ + row0) * D_;
        const int w = tid >> 5;
        __nv_bfloat16* Ah = (__nv_bfloat16*)smf;
        __nv_bfloat16* Al = Ah + 64 * LDA;
        float* gates = smf + F_GATES;

        if (isA) {
            bsum[tid] = bih1[tid] + bhh1[tid];
            stage_a(Ah, Al, tid, g_vh0[old] + base, g_vh1[old] + base);
            __syncthreads();
            wmma_gemm(Ah, Al, g_W1hi, g_W1lo, gates, w);
            __syncthreads();
            lstm_act(gates, bsum, g_vc1[old] + base,
                     g_vh1[nw] + base, g_vc1[nw] + base, tid);
        } else {
            bsum[tid] = g_mcg[b * 256 + tid];
            stage_a(Ah, Al, tid, g_mv + base, g_vh0[old] + base);
            __syncthreads();
            wmma_gemm(Ah, Al, g_W0hi, g_W0lo, gates, w);
            __syncthreads();
            lstm_act(gates, bsum, g_vc0[old] + base,
                     g_vh0[nw] + base, g_vc0[nw] + base, tid);
        }
    } else {
        // ----- C2 role: vsum + xps + LSTMc -----
        const int b = bid - 1024;
        const int nc = n_colors[b];
        float* vsum = smf;            // 64
        float* xps  = smf + 64;       // 256
        float* chs  = smf + 320;      // 1024
        float* gcs  = smf + 1344;     // 4160

        if (tid < 64) {
            float s = 0.f;
            #pragma unroll
            for (int blk = 0; blk < 8; blk++) s += g_vpart[(b * 8 + blk) * 64 + tid];
            vsum[tid] = s;
        }
        {
            const float4* pc = (const float4*)(g_ch[old] + b * 1024);
            for (int i = tid; i < 256; i += 256) ((float4*)chs)[i] = pc[i];
        }
        __syncthreads();
        {
            int g = tid;
            float x0 = 0.f, x1 = 0.f;
            #pragma unroll 8
            for (int d = 0; d < 64; d += 2) {
                x0 = fmaf(vsum[d],     Wihc[d * 256 + g],       x0);
                x1 = fmaf(vsum[d + 1], Wihc[(d + 1) * 256 + g], x1);
            }
            xps[g] = x0 + x1;
        }
        __syncthreads();
        {
            int c = tid >> 4, seg = (tid & 15) * 16;
            float a[16];
            #pragma unroll
            for (int i = 0; i < 16; i++) a[i] = 0.f;
            for (int k = 0; k < 64; k++) {
                float x = chs[c * 64 + k];
                const float4* wrow = (const float4*)(Whhc + k * 256 + seg);
                float4 w0 = wrow[0], w1 = wrow[1], w2 = wrow[2], w3 = wrow[3];
                a[0]  = fmaf(x, w0.x, a[0]);  a[1]  = fmaf(x, w0.y, a[1]);
                a[2]  = fmaf(x, w0.z, a[2]);  a[3]  = fmaf(x, w0.w, a[3]);
                a[4]  = fmaf(x, w1.x, a[4]);  a[5]  = fmaf(x, w1.y, a[5]);
                a[6]  = fmaf(x, w1.z, a[6]);  a[7]  = fmaf(x, w1.w, a[7]);
                a[8]  = fmaf(x, w2.x, a[8]);  a[9]  = fmaf(x, w2.y, a[9]);
                a[10] = fmaf(x, w2.z, a[10]); a[11] = fmaf(x, w2.w, a[11]);
                a[12] = fmaf(x, w3.x, a[12]); a[13] = fmaf(x, w3.y, a[13]);
                a[14] = fmaf(x, w3.z, a[14]); a[15] = fmaf(x, w3.w, a[15]);
            }
            float mk = (c < nc) ? 1.f : 0.f;
            #pragma unroll
            for (int i = 0; i < 16; i++) {
                int g = seg + i;
                gcs[c * 260 + g] = a[i] + mk * xps[g] + bihc[g] + bhhc[g];
            }
        }
        __syncthreads();
        {
            const float* cco = g_cc[old] + b * 1024;
            float* chn = g_ch[nw] + b * 1024;
            float* ccn = g_cc[nw] + b * 1024;
            for (int i = tid; i < 1024; i += 256) {
                int c = i >> 6, d = i & 63;
                float gi  = gcs[c * 260 + d];
                float gf  = gcs[c * 260 + 64 + d];
                float gg2 = gcs[c * 260 + 128 + d];
                float go  = gcs[c * 260 + 192 + d];
                float c2 = sigf(gf) * cco[i] + sigf(gi) * tanhfast(gg2);
                ccn[i] = c2;
                chn[i] = sigf(go) * tanhfast(c2);
            }
        }
    }
}

// ---------------- vote head ----------------------------------------------
__global__ void k_vote(const float* __restrict__ W1, const float* __restrict__ b1,
                       const float* __restrict__ W2, const float* __restrict__ b2,
                       float* __restrict__ out)
{
    __shared__ float w1s[64 * 16];
    __shared__ float w2s[16];
    __shared__ float red[256];
    const int tid = threadIdx.x, b = blockIdx.x;
    for (int i = tid; i < 64 * 16; i += 256) w1s[i] = W1[i];
    if (tid < 16) w2s[tid] = W2[tid];
    __syncthreads();

    float acc = 0.f;
    for (int r = tid; r < N_; r += 256) {
        const float* x = g_vh1[0] + ((size_t)b * N_ + r) * D_;
        float h[16];
        #pragma unroll
        for (int j = 0; j < 16; j++) h[j] = b1[j];
        for (int k = 0; k < 64; k++) {
            float xv = x[k];
            #pragma unroll
            for (int j = 0; j < 16; j++) h[j] = fmaf(xv, w1s[k * 16 + j], h[j]);
        }
        float v = b2[0];
        #pragma unroll
        for (int j = 0; j < 16; j++) v += sigf(h[j]) * w2s[j];
        acc += sigf(v);
    }
    red[tid] = acc;
    __syncthreads();
    for (int s = 128; s > 0; s >>= 1) {
        if (tid < s) red[tid] += red[tid + s];
        __syncthreads();
    }
    if (tid == 0) out[b] = sigf(red[0] / (float)N_);
}

// ---------------- launch -------------------------------------------------
extern "C" void kernel_launch(void* const* d_in, const int* in_sizes, int n_in,
                              void* d_out, int out_size)
{
    const float* Mvv      = (const float*)d_in[0];
    const int*   n_colors = (const int*)d_in[1];
    const float* vh0i     = (const float*)d_in[2];
    const float* vh1i     = (const float*)d_in[3];
    const float* chi      = (const float*)d_in[4];
    const float* Wih0 = (const float*)d_in[5];
    const float* Whh0 = (const float*)d_in[6];
    const float* bih0 = (const float*)d_in[7];
    const float* bhh0 = (const float*)d_in[8];
    const float* Wih1 = (const float*)d_in[9];
    const float* Whh1 = (const float*)d_in[10];
    const float* bih1 = (const float*)d_in[11];
    const float* bhh1 = (const float*)d_in[12];
    const float* Wihc = (const float*)d_in[13];
    const float* Whhc = (const float*)d_in[14];
    const float* bihc = (const float*)d_in[15];
    const float* bhhc = (const float*)d_in[16];
    const float* cW1 = (const float*)d_in[17];
    const float* cb1 = (const float*)d_in[18];
    const float* cW2 = (const float*)d_in[19];
    const float* cb2 = (const float*)d_in[20];
    const float* vW1 = (const float*)d_in[21];
    const float* vb1 = (const float*)d_in[22];
    const float* vW2 = (const float*)d_in[23];
    const float* vb2 = (const float*)d_in[24];
    const float* voteW1 = (const float*)d_in[25];
    const float* voteb1 = (const float*)d_in[26];
    const float* voteW2 = (const float*)d_in[27];
    const float* voteb2 = (const float*)d_in[28];
    float* out = (float*)d_out;

    cudaFuncSetAttribute(k_front, cudaFuncAttributeMaxDynamicSharedMemorySize, SMEM_GM);
    cudaFuncSetAttribute(k_back,  cudaFuncAttributeMaxDynamicSharedMemorySize, SMEM_AB);

    k_adj<<<(B_ * N_ * 32 + 255) / 256, 256>>>(Mvv);
    k_init<<<(VND + 255) / 256, 256>>>(vh0i, vh1i, chi);
    k_prepw<<<256, 256>>>(Wih0, Whh0, Wih1, Whh1);

    for (int t = 0; t < T_; t++) {
        int old = t & 1;
        k_front<<<576, 256, SMEM_GM>>>(old, vW1, vb1, vW2, vb2, n_colors,
                                       cW1, cb1, cW2, cb2, Wih0, bih0, bhh0);
        k_back<<<1088, 256, SMEM_AB>>>(old, bih1, bhh1, n_colors,
                                       Wihc, Whhc, bihc, bhhc);
    }
    k_vote<<<B_, 256>>>(voteW1, voteb1, voteW2, voteb2, out);
}

// round 16
// speedup vs baseline: 1.3391x; 1.0373x over previous
#include <cuda_runtime.h>
#include <cuda_bf16.h>
#include <mma.h>
#include <cstdint>
#include <cstddef>
#include <math.h>

using namespace nvcuda;

constexpr int B_ = 64, N_ = 512, C_ = 16, D_ = 64, T_ = 32;
constexpr int VND = B_ * N_ * D_;
constexpr int CDD = B_ * C_ * D_;
constexpr int MAXDEG = 160;

constexpr int LDA = 136;   // smem A tile [64][LDA] bf16 (bank-spread padding)
constexpr int LDG_ = 272;  // gates [64][LDG_] f32

// ---------------- state (device globals; allocation-free) ----------------
__device__ float g_vh0[2][VND];
__device__ float g_vh1[2][VND];
__device__ float g_vc0[2][VND];
__device__ float g_vc1[2][VND];
__device__ float g_ch[2][CDD];
__device__ float g_cc[2][CDD];
__device__ float g_mv[VND];
__device__ float g_vpart[B_ * 8 * 64];
__device__ float g_mcg[B_ * 256];
__device__ unsigned short g_nbr[(size_t)B_ * N_ * MAXDEG];
__device__ int g_deg[B_ * N_];
__device__ __nv_bfloat16 g_W1hi[32768], g_W1lo[32768];
__device__ __nv_bfloat16 g_W0hi[32768], g_W0lo[32768];

__device__ __forceinline__ float sigf(float x)     { return 1.0f / (1.0f + __expf(-x)); }
__device__ __forceinline__ float tanhfast(float x) { return 2.0f / (1.0f + __expf(-2.0f * x)) - 1.0f; }

// ---------------- adjacency build ----------------
__global__ void k_adj(const float* __restrict__ Mvv)
{
    int gw = (blockIdx.x * blockDim.x + threadIdx.x) >> 5;
    int lane = threadIdx.x & 31;
    if (gw >= B_ * N_) return;
    const float* row = Mvv + (size_t)gw * N_;
    unsigned short* outp = g_nbr + (size_t)gw * MAXDEG;
    int cnt = 0;
    for (int base = 0; base < N_; base += 32) {
        float v = row[base + lane];
        unsigned m = __ballot_sync(0xffffffffu, v != 0.0f);
        if (v != 0.0f) {
            int pos = cnt + __popc(m & ((1u << lane) - 1u));
            if (pos < MAXDEG) outp[pos] = (unsigned short)(base + lane);
        }
        cnt += __popc(m);
    }
    if (lane == 0) g_deg[gw] = cnt < MAXDEG ? cnt : MAXDEG;
}

__global__ void k_init(const float* __restrict__ vh0i, const float* __restrict__ vh1i,
                       const float* __restrict__ chi)
{
    int i = blockIdx.x * blockDim.x + threadIdx.x;
    if (i < VND) {
        g_vh0[0][i] = vh0i[i];
        g_vh1[0][i] = vh1i[i];
        g_vc0[0][i] = 0.f;
        g_vc1[0][i] = 0.f;
    }
    if (i < CDD) { g_ch[0][i] = chi[i]; g_cc[0][i] = 0.f; }
}

// ---------------- weight image build (once per replay) -------------------
__global__ void k_prepw(const float* __restrict__ Wih0, const float* __restrict__ Whh0,
                        const float* __restrict__ Wih1, const float* __restrict__ Whh1)
{
    int idx = blockIdx.x * blockDim.x + threadIdx.x;
    if (idx >= 65536) return;
    int mat = idx >> 15;
    int rem = idx & 32767;
    int k = rem >> 8;
    int n = rem & 255;
    float v;
    if (mat == 0) v = (k < 64) ? Wih1[k * 256 + n]        : Whh1[(k - 64) * 256 + n];
    else          v = (k < 64) ? Wih0[(64 + k) * 256 + n] : Whh0[(k - 64) * 256 + n];
    __nv_bfloat16 h = __float2bfloat16(v);
    __nv_bfloat16 l = __float2bfloat16(v - __bfloat162float(h));
    if (mat == 0) { g_W1hi[k * 256 + n] = h; g_W1lo[k * 256 + n] = l; }
    else          { g_W0hi[k * 256 + n] = h; g_W0lo[k * 256 + n] = l; }
}

// stage two fp32 sources as bf16 hi/lo A tile [64][LDA]
__device__ __forceinline__ void stage_a(__nv_bfloat16* Ah, __nv_bfloat16* Al, int tid,
                                        const float* src0, const float* src1)
{
    for (int i = tid; i < 4096; i += 256) {
        int r = i >> 6, k = (i & 63) * 2;
        float2 v = (k < 64) ? *(const float2*)(src0 + r * 64 + k)
                            : *(const float2*)(src1 + r * 64 + k - 64);
        __nv_bfloat162 h2 = __float22bfloat162_rn(v);
        float2 bk; bk.x = __bfloat162float(h2.x); bk.y = __bfloat162float(h2.y);
        float2 lo; lo.x = v.x - bk.x; lo.y = v.y - bk.y;
        __nv_bfloat162 l2 = __float22bfloat162_rn(lo);
        *(__nv_bfloat162*)(Ah + r * LDA + k) = h2;
        *(__nv_bfloat162*)(Al + r * LDA + k) = l2;
    }
}

// wmma GEMM: gates[64][LDG_] = A[64][128](smem) @ W[128][256](global), 3-term hi/lo
__device__ __forceinline__ void wmma_gemm(const __nv_bfloat16* Ah, const __nv_bfloat16* Al,
                                          const __nv_bfloat16* __restrict__ Wh,
                                          const __nv_bfloat16* __restrict__ Wl,
                                          float* gates, int w)
{
    int rowtile = w >> 1;
    wmma::fragment<wmma::matrix_a, 16, 16, 16, __nv_bfloat16, wmma::row_major> aHi, aLo;
    wmma::fragment<wmma::matrix_b, 16, 16, 16, __nv_bfloat16, wmma::row_major> bHi, bLo;
    #pragma unroll
    for (int cg = 0; cg < 2; cg++) {
        int colbase = (w & 1) * 128 + cg * 64;
        wmma::fragment<wmma::accumulator, 16, 16, 16, float> acc[4];
        #pragma unroll
        for (int ct = 0; ct < 4; ct++) wmma::fill_fragment(acc[ct], 0.0f);
        #pragma unroll
        for (int k = 0; k < 8; k++) {
            wmma::load_matrix_sync(aHi, Ah + rowtile * 16 * LDA + k * 16, LDA);
            wmma::load_matrix_sync(aLo, Al + rowtile * 16 * LDA + k * 16, LDA);
            #pragma unroll
            for (int ct = 0; ct < 4; ct++) {
                const __nv_bfloat16* bp = Wh + (k * 16) * 256 + colbase + ct * 16;
                const __nv_bfloat16* bq = Wl + (k * 16) * 256 + colbase + ct * 16;
                wmma::load_matrix_sync(bHi, bp, 256);
                wmma::load_matrix_sync(bLo, bq, 256);
                wmma::mma_sync(acc[ct], aHi, bHi, acc[ct]);
                wmma::mma_sync(acc[ct], aHi, bLo, acc[ct]);
                wmma::mma_sync(acc[ct], aLo, bHi, acc[ct]);
            }
        }
        #pragma unroll
        for (int ct = 0; ct < 4; ct++)
            wmma::store_matrix_sync(gates + rowtile * 16 * LDG_ + colbase + ct * 16,
                                    acc[ct], LDG_, wmma::mem_row_major);
    }
}

// shared LSTM epilogue
__device__ __forceinline__ void lstm_act(const float* gates, const float* bsum,
                                         const float* c_old, float* h_new, float* c_new,
                                         int tid)
{
    for (int i = tid; i < 4096; i += 256) {
        int r = i >> 6, d = i & 63;
        float gi = gates[r * LDG_ + d]       + bsum[d];
        float gf = gates[r * LDG_ + 64 + d]  + bsum[64 + d];
        float gg = gates[r * LDG_ + 128 + d] + bsum[128 + d];
        float go = gates[r * LDG_ + 192 + d] + bsum[192 + d];
        float c2 = sigf(gf) * c_old[i] + sigf(gi) * tanhfast(gg);
        c_new[i] = c2;
        h_new[i] = sigf(go) * tanhfast(c2);
    }
}

// ================= kernel FRONT: gm (512 blocks) + C1/mcg (64 blocks) ====
// MLP weights read from global (L2-hot, shared by all blocks).
// smem floats: X1@0 (4352), H@4352 (6656), R@11008 (256) -> 11264 f = 45,056 B
// 4 blocks/SM (regs 52: 4*256*52 = 53.2K < 64K; smem 4*45 = 180K < 227K)
constexpr int SMEM_GM = 11264 * 4;
constexpr int GM_X1 = 0, GM_H = 4352, GM_R = 11008;

__global__ __launch_bounds__(256, 4)
void k_front(int old, const float* __restrict__ vW1, const float* __restrict__ vb1,
             const float* __restrict__ vW2, const float* __restrict__ vb2,
             const int* __restrict__ n_colors,
             const float* __restrict__ cW1, const float* __restrict__ cb1,
             const float* __restrict__ cW2, const float* __restrict__ cb2,
             const float* __restrict__ Wih0, const float* __restrict__ bih0,
             const float* __restrict__ bhh0)
{
    extern __shared__ float smf[];
    const int tid = threadIdx.x;

    if (blockIdx.x < 512) {
        // ----- gm role: mv gather + vmsg MLP -----
        const int lane = tid & 31, w = tid >> 5;
        const int b = blockIdx.x >> 3;
        const int tile = blockIdx.x & 7;
        const int row0 = tile * 64;
        const size_t base = ((size_t)b * N_ + row0) * D_;

        {
            const float4* px = (const float4*)(g_vh1[old] + base);
            for (int i = tid; i < 1024; i += 256) {
                int r = i >> 4, q = i & 15;
                *(float4*)(smf + GM_X1 + r * 68 + q * 4) = px[i];
            }
        }
        // sparse mv gather
        {
            const float* vh1b = g_vh1[old] + (size_t)b * N_ * D_;
            for (int r = w; r < 64; r += 8) {
                int n = row0 + r;
                int deg = g_deg[b * N_ + n];
                const unsigned short* nb = g_nbr + ((size_t)(b * N_ + n)) * MAXDEG;
                float a0 = 0.f, a1 = 0.f, b0 = 0.f, b1 = 0.f, c0 = 0.f, c1 = 0.f, d0 = 0.f, d1 = 0.f;
                int k = 0;
                for (; k + 4 <= deg; k += 4) {
                    float2 v0 = *(const float2*)(vh1b + (size_t)nb[k]     * D_ + lane * 2);
                    float2 v1 = *(const float2*)(vh1b + (size_t)nb[k + 1] * D_ + lane * 2);
                    float2 v2 = *(const float2*)(vh1b + (size_t)nb[k + 2] * D_ + lane * 2);
                    float2 v3 = *(const float2*)(vh1b + (size_t)nb[k + 3] * D_ + lane * 2);
                    a0 += v0.x; a1 += v0.y; b0 += v1.x; b1 += v1.y;
                    c0 += v2.x; c1 += v2.y; d0 += v3.x; d1 += v3.y;
                }
                for (; k < deg; k++) {
                    float2 v = *(const float2*)(vh1b + (size_t)nb[k] * D_ + lane * 2);
                    a0 += v.x; a1 += v.y;
                }
                *((float2*)(g_mv + ((size_t)b * N_ + n) * D_) + lane) =
                    make_float2(a0 + b0 + c0 + d0, a1 + b1 + c1 + d1);
            }
        }
        __syncthreads();

        // MLP layer 1 (W1 from global, quad-blocked)
        {
            float* X1 = smf + GM_X1;
            float* H  = smf + GM_H;
            for (int idx = tid; idx < 1600; idx += 256) {
                int r = idx / 25, q = idx - r * 25;
                float ax = 0.f, ay = 0.f, az = 0.f, aw = 0.f;
                #pragma unroll 4
                for (int k = 0; k < 64; k++) {
                    float x = X1[r * 68 + k];
                    float4 wv = *(const float4*)(vW1 + k * 100 + q * 4);
                    ax = fmaf(x, wv.x, ax);
                    ay = fmaf(x, wv.y, ay);
                    az = fmaf(x, wv.z, az);
                    aw = fmaf(x, wv.w, aw);
                }
                int h = q * 4;
                H[r * 104 + h + 0] = fmaxf(ax + vb1[h + 0], 0.f);
                H[r * 104 + h + 1] = fmaxf(ay + vb1[h + 1], 0.f);
                H[r * 104 + h + 2] = fmaxf(az + vb1[h + 2], 0.f);
                H[r * 104 + h + 3] = fmaxf(aw + vb1[h + 3], 0.f);
            }
        }
        __syncthreads();
        // layer 2 (W2 from global) + relu into V (=X1 region)
        {
            float* H = smf + GM_H;
            float* V = smf + GM_X1;
            for (int idx = tid; idx < 1024; idx += 256) {
                int r = idx >> 4, q = idx & 15;
                float ax = 0.f, ay = 0.f, az = 0.f, aw = 0.f;
                #pragma unroll 4
                for (int k = 0; k < 100; k++) {
                    float x = H[r * 104 + k];
                    float4 wv = *(const float4*)(vW2 + k * 64 + q * 4);
                    ax = fmaf(x, wv.x, ax);
                    ay = fmaf(x, wv.y, ay);
                    az = fmaf(x, wv.z, az);
                    aw = fmaf(x, wv.w, aw);
                }
                int d = q * 4;
                V[r * 68 + d + 0] = fmaxf(ax + vb2[d + 0], 0.f);
                V[r * 68 + d + 1] = fmaxf(ay + vb2[d + 1], 0.f);
                V[r * 68 + d + 2] = fmaxf(az + vb2[d + 2], 0.f);
                V[r * 68 + d + 3] = fmaxf(aw + vb2[d + 3], 0.f);
            }
        }
        __syncthreads();
        {
            float* V = smf + GM_X1;
            float* R = smf + GM_R;
            int q = tid >> 6, d = tid & 63;
            float s = 0.f;
            #pragma unroll
            for (int r = 0; r < 16; r++) s += V[(q * 16 + r) * 68 + d];
            R[q * 64 + d] = s;
            __syncthreads();
            if (tid < 64)
                g_vpart[(b * 8 + tile) * 64 + tid] =
                    R[tid] + R[64 + tid] + R[128 + tid] + R[192 + tid];
        }
    } else {
        // ----- C1 role: cmsg MLP + mcg (ch_old only; weights from global) -----
        const int b = blockIdx.x - 512;
        const int nc = n_colors[b];
        float* chs   = smf;            // 1024
        float* hid   = smf + 1024;     // 1664
        float* cmsgs = smf + 2688;     // 1024
        float* mcv   = smf + 3712;     // 64

        {
            const float4* pc = (const float4*)(g_ch[old] + b * 1024);
            for (int i = tid; i < 256; i += 256) ((float4*)chs)[i] = pc[i];
        }
        __syncthreads();

        for (int idx = tid; idx < 400; idx += 256) {
            int c = idx / 25, q = idx - c * 25;
            float ax = 0.f, ay = 0.f, az = 0.f, aw = 0.f;
            #pragma unroll 4
            for (int k = 0; k < 64; k++) {
                float x = chs[c * 64 + k];
                float4 wv = *(const float4*)(cW1 + k * 100 + q * 4);
                ax = fmaf(x, wv.x, ax);
                ay = fmaf(x, wv.y, ay);
                az = fmaf(x, wv.z, az);
                aw = fmaf(x, wv.w, aw);
            }
            int h = q * 4;
            hid[c * 104 + h + 0] = fmaxf(ax + cb1[h + 0], 0.f);
            hid[c * 104 + h + 1] = fmaxf(ay + cb1[h + 1], 0.f);
            hid[c * 104 + h + 2] = fmaxf(az + cb1[h + 2], 0.f);
            hid[c * 104 + h + 3] = fmaxf(aw + cb1[h + 3], 0.f);
        }
        __syncthreads();
        {
            int c = tid >> 4, q = tid & 15;
            float ax = 0.f, ay = 0.f, az = 0.f, aw = 0.f;
            #pragma unroll 4
            for (int k = 0; k < 100; k++) {
                float x = hid[c * 104 + k];
                float4 wv = *(const float4*)(cW2 + k * 64 + q * 4);
                ax = fmaf(x, wv.x, ax);
                ay = fmaf(x, wv.y, ay);
                az = fmaf(x, wv.z, az);
                aw = fmaf(x, wv.w, aw);
            }
            int d = q * 4;
            cmsgs[c * 64 + d + 0] = fmaxf(ax + cb2[d + 0], 0.f);
            cmsgs[c * 64 + d + 1] = fmaxf(ay + cb2[d + 1], 0.f);
            cmsgs[c * 64 + d + 2] = fmaxf(az + cb2[d + 2], 0.f);
            cmsgs[c * 64 + d + 3] = fmaxf(aw + cb2[d + 3], 0.f);
        }
        __syncthreads();
        if (tid < 64) {
            float s = 0.f;
            for (int c = 0; c < nc; c++) s += cmsgs[c * 64 + tid];
            mcv[tid] = s;
        }
        __syncthreads();
        {
            int g = tid;
            float a0 = bih0[g] + bhh0[g], a1 = 0.f;
            #pragma unroll 8
            for (int d = 0; d < 64; d += 2) {
                a0 = fmaf(mcv[d],     Wih0[d * 256 + g],       a0);
                a1 = fmaf(mcv[d + 1], Wih0[(d + 1) * 256 + g], a1);
            }
            g_mcg[b * 256 + g] = a0 + a1;
        }
    }
}

// ================= kernel BACK: A2 (512) + B (512) + C2 (64) =============
constexpr int SMEM_AB = 26112 * 4;
constexpr int F_GATES = 8704;

__global__ __launch_bounds__(256, 2)
void k_back(int old, const float* __restrict__ bih1, const float* __restrict__ bhh1,
            const int* __restrict__ n_colors,
            const float* __restrict__ Wihc, const float* __restrict__ Whhc,
            const float* __restrict__ bihc, const float* __restrict__ bhhc)
{
    extern __shared__ float smf[];
    __shared__ float bsum[256];
    const int tid = threadIdx.x;
    const int bid = blockIdx.x;
    const int nw = 1 - old;

    if (bid < 1024) {
        const bool isA = (bid < 512);
        const int lb = isA ? bid : bid - 512;
        const int b = lb >> 3;
        const int tile = lb & 7;
        const int row0 = tile * 64;
        const size_t base = ((size_t)b * N_ + row0) * D_;
        const int w = tid >> 5;
        __nv_bfloat16* Ah = (__nv_bfloat16*)smf;
        __nv_bfloat16* Al = Ah + 64 * LDA;
        float* gates = smf + F_GATES;

        if (isA) {
            bsum[tid] = bih1[tid] + bhh1[tid];
            stage_a(Ah, Al, tid, g_vh0[old] + base, g_vh1[old] + base);
            __syncthreads();
            wmma_gemm(Ah, Al, g_W1hi, g_W1lo, gates, w);
            __syncthreads();
            lstm_act(gates, bsum, g_vc1[old] + base,
                     g_vh1[nw] + base, g_vc1[nw] + base, tid);
        } else {
            bsum[tid] = g_mcg[b * 256 + tid];
            stage_a(Ah, Al, tid, g_mv + base, g_vh0[old] + base);
            __syncthreads();
            wmma_gemm(Ah, Al, g_W0hi, g_W0lo, gates, w);
            __syncthreads();
            lstm_act(gates, bsum, g_vc0[old] + base,
                     g_vh0[nw] + base, g_vc0[nw] + base, tid);
        }
    } else {
        // ----- C2 role: vsum + xps + LSTMc -----
        const int b = bid - 1024;
        const int nc = n_colors[b];
        float* vsum = smf;            // 64
        float* xps  = smf + 64;       // 256
        float* chs  = smf + 320;      // 1024
        float* gcs  = smf + 1344;     // 4160

        if (tid < 64) {
            float s = 0.f;
            #pragma unroll
            for (int blk = 0; blk < 8; blk++) s += g_vpart[(b * 8 + blk) * 64 + tid];
            vsum[tid] = s;
        }
        {
            const float4* pc = (const float4*)(g_ch[old] + b * 1024);
            for (int i = tid; i < 256; i += 256) ((float4*)chs)[i] = pc[i];
        }
        __syncthreads();
        {
            int g = tid;
            float x0 = 0.f, x1 = 0.f;
            #pragma unroll 8
            for (int d = 0; d < 64; d += 2) {
                x0 = fmaf(vsum[d],     Wihc[d * 256 + g],       x0);
                x1 = fmaf(vsum[d + 1], Wihc[(d + 1) * 256 + g], x1);
            }
            xps[g] = x0 + x1;
        }
        __syncthreads();
        {
            int c = tid >> 4, seg = (tid & 15) * 16;
            float a[16];
            #pragma unroll
            for (int i = 0; i < 16; i++) a[i] = 0.f;
            for (int k = 0; k < 64; k++) {
                float x = chs[c * 64 + k];
                const float4* wrow = (const float4*)(Whhc + k * 256 + seg);
                float4 w0 = wrow[0], w1 = wrow[1], w2 = wrow[2], w3 = wrow[3];
                a[0]  = fmaf(x, w0.x, a[0]);  a[1]  = fmaf(x, w0.y, a[1]);
                a[2]  = fmaf(x, w0.z, a[2]);  a[3]  = fmaf(x, w0.w, a[3]);
                a[4]  = fmaf(x, w1.x, a[4]);  a[5]  = fmaf(x, w1.y, a[5]);
                a[6]  = fmaf(x, w1.z, a[6]);  a[7]  = fmaf(x, w1.w, a[7]);
                a[8]  = fmaf(x, w2.x, a[8]);  a[9]  = fmaf(x, w2.y, a[9]);
                a[10] = fmaf(x, w2.z, a[10]); a[11] = fmaf(x, w2.w, a[11]);
                a[12] = fmaf(x, w3.x, a[12]); a[13] = fmaf(x, w3.y, a[13]);
                a[14] = fmaf(x, w3.z, a[14]); a[15] = fmaf(x, w3.w, a[15]);
            }
            float mk = (c < nc) ? 1.f : 0.f;
            #pragma unroll
            for (int i = 0; i < 16; i++) {
                int g = seg + i;
                gcs[c * 260 + g] = a[i] + mk * xps[g] + bihc[g] + bhhc[g];
            }
        }
        __syncthreads();
        {
            const float* cco = g_cc[old] + b * 1024;
            float* chn = g_ch[nw] + b * 1024;
            float* ccn = g_cc[nw] + b * 1024;
            for (int i = tid; i < 1024; i += 256) {
                int c = i >> 6, d = i & 63;
                float gi  = gcs[c * 260 + d];
                float gf  = gcs[c * 260 + 64 + d];
                float gg2 = gcs[c * 260 + 128 + d];
                float go  = gcs[c * 260 + 192 + d];
                float c2 = sigf(gf) * cco[i] + sigf(gi) * tanhfast(gg2);
                ccn[i] = c2;
                chn[i] = sigf(go) * tanhfast(c2);
            }
        }
    }
}

// ---------------- vote head ----------------------------------------------
__global__ void k_vote(const float* __restrict__ W1, const float* __restrict__ b1,
                       const float* __restrict__ W2, const float* __restrict__ b2,
                       float* __restrict__ out)
{
    __shared__ float w1s[64 * 16];
    __shared__ float w2s[16];
    __shared__ float red[256];
    const int tid = threadIdx.x, b = blockIdx.x;
    for (int i = tid; i < 64 * 16; i += 256) w1s[i] = W1[i];
    if (tid < 16) w2s[tid] = W2[tid];
    __syncthreads();

    float acc = 0.f;
    for (int r = tid; r < N_; r += 256) {
        const float* x = g_vh1[0] + ((size_t)b * N_ + r) * D_;
        float h[16];
        #pragma unroll
        for (int j = 0; j < 16; j++) h[j] = b1[j];
        for (int k = 0; k < 64; k++) {
            float xv = x[k];
            #pragma unroll
            for (int j = 0; j < 16; j++) h[j] = fmaf(xv, w1s[k * 16 + j], h[j]);
        }
        float v = b2[0];
        #pragma unroll
        for (int j = 0; j < 16; j++) v += sigf(h[j]) * w2s[j];
        acc += sigf(v);
    }
    red[tid] = acc;
    __syncthreads();
    for (int s = 128; s > 0; s >>= 1) {
        if (tid < s) red[tid] += red[tid + s];
        __syncthreads();
    }
    if (tid == 0) out[b] = sigf(red[0] / (float)N_);
}

// ---------------- launch -------------------------------------------------
extern "C" void kernel_launch(void* const* d_in, const int* in_sizes, int n_in,
                              void* d_out, int out_size)
{
    const float* Mvv      = (const float*)d_in[0];
    const int*   n_colors = (const int*)d_in[1];
    const float* vh0i     = (const float*)d_in[2];
    const float* vh1i     = (const float*)d_in[3];
    const float* chi      = (const float*)d_in[4];
    const float* Wih0 = (const float*)d_in[5];
    const float* Whh0 = (const float*)d_in[6];
    const float* bih0 = (const float*)d_in[7];
    const float* bhh0 = (const float*)d_in[8];
    const float* Wih1 = (const float*)d_in[9];
    const float* Whh1 = (const float*)d_in[10];
    const float* bih1 = (const float*)d_in[11];
    const float* bhh1 = (const float*)d_in[12];
    const float* Wihc = (const float*)d_in[13];
    const float* Whhc = (const float*)d_in[14];
    const float* bihc = (const float*)d_in[15];
    const float* bhhc = (const float*)d_in[16];
    const float* cW1 = (const float*)d_in[17];
    const float* cb1 = (const float*)d_in[18];
    const float* cW2 = (const float*)d_in[19];
    const float* cb2 = (const float*)d_in[20];
    const float* vW1 = (const float*)d_in[21];
    const float* vb1 = (const float*)d_in[22];
    const float* vW2 = (const float*)d_in[23];
    const float* vb2 = (const float*)d_in[24];
    const float* voteW1 = (const float*)d_in[25];
    const float* voteb1 = (const float*)d_in[26];
    const float* voteW2 = (const float*)d_in[27];
    const float* voteb2 = (const float*)d_in[28];
    float* out = (float*)d_out;

    cudaFuncSetAttribute(k_front, cudaFuncAttributeMaxDynamicSharedMemorySize, SMEM_GM);
    cudaFuncSetAttribute(k_back,  cudaFuncAttributeMaxDynamicSharedMemorySize, SMEM_AB);

    k_adj<<<(B_ * N_ * 32 + 255) / 256, 256>>>(Mvv);
    k_init<<<(VND + 255) / 256, 256>>>(vh0i, vh1i, chi);
    k_prepw<<<256, 256>>>(Wih0, Whh0, Wih1, Whh1);

    for (int t = 0; t < T_; t++) {
        int old = t & 1;
        k_front<<<576, 256, SMEM_GM>>>(old, vW1, vb1, vW2, vb2, n_colors,
                                       cW1, cb1, cW2, cb2, Wih0, bih0, bhh0);
        k_back<<<1088, 256, SMEM_AB>>>(old, bih1, bhh1, n_colors,
                                       Wihc, Whhc, bihc, bhhc);
    }
    k_vote<<<B_, 256>>>(voteW1, voteb1, voteW2, voteb2, out);
}